// round 8
// baseline (speedup 1.0000x reference)
#include <cuda_runtime.h>
#include <cuda_fp16.h>
#include <cstdint>

#define H       128
#define NHEAD   8
#define N_MAX   50000
#define NRELMX  64
#define TEN     32
#define GPAD    36
#define TILE_E  64
#define NT      256

// ---------------- global scratch -------------------------------------------
__device__ float g_Q  [N_MAX * H];
__device__ float g_S1 [N_MAX * H];
__device__ float g_R2x[NRELMX * H];
__device__ float g_denom[N_MAX * NHEAD];
__device__ __half g_B[256 * H];   // [n][k] fp16, 256B rows, XOR-16B swizzle

// ---------------- smem layout ----------------------------------------------
#define OFF_B     0        // 65536
#define OFF_A     65536    // 16384 (fp16 A tile, 64 x 256B)
#define OFF_KV    65536    // 32768, aliases A (used after GEMM)
#define OFF_BK    98304
#define OFF_BV    98816
#define OFF_B1    99328
#define OFF_W2    99840
#define OFF_DST   100352
#define OFF_SRC   100608
#define OFF_ET    100864
#define OFF_TM    101120
#define OFF_SS    101376
#define OFF_WS    101632   // w_sm[64][8] = 2048
#define SMEM_EDGE 103680

// ---------------- helpers --------------------------------------------------
__device__ __forceinline__ uint32_t s2u(const void* p) {
    uint32_t a;
    asm("{ .reg .u64 t; cvta.to.shared.u64 t, %1; cvt.u32.u64 %0, t; }" : "=r"(a) : "l"(p));
    return a;
}
__device__ __forceinline__ void ldsm4(uint32_t* r, uint32_t addr) {
    asm volatile("ldmatrix.sync.aligned.m8n8.x4.shared.b16 {%0,%1,%2,%3}, [%4];"
                 : "=r"(r[0]), "=r"(r[1]), "=r"(r[2]), "=r"(r[3]) : "r"(addr));
}
__device__ __forceinline__ void mma16816(float* c, const uint32_t* a, const uint32_t* b) {
    asm volatile(
        "mma.sync.aligned.m16n8k16.row.col.f32.f16.f16.f32 "
        "{%0,%1,%2,%3}, {%4,%5,%6,%7}, {%8,%9}, {%0,%1,%2,%3};"
        : "+f"(c[0]), "+f"(c[1]), "+f"(c[2]), "+f"(c[3])
        : "r"(a[0]), "r"(a[1]), "r"(a[2]), "r"(a[3]), "r"(b[0]), "r"(b[1]));
}
#define DUP2(d, s) asm("mov.b64 %0, {%1,%1};" : "=l"(d) : "f"(s))
#define F2MA(acc, a, b) asm("fma.rn.f32x2 %0, %1, %2, %0;" : "+l"(acc) : "l"(a), "l"(b))

// ---------------- init -----------------------------------------------------
__global__ void k_init(float* __restrict__ out, int N, int outElems) {
    int i = blockIdx.x * blockDim.x + threadIdx.x;
    int stride = gridDim.x * blockDim.x;
    for (int idx = i; idx < outElems; idx += stride) out[idx] = 0.f;
    for (int idx = i; idx < N * NHEAD; idx += stride) g_denom[idx] = 0.f;
}

// ---------------- R2x[r] = rel[r] @ W1[128:256] + W1[256] ------------------
__global__ void k_rel(const float* __restrict__ rel, const float* __restrict__ W1) {
    int r = blockIdx.x, j = threadIdx.x;
    float acc = W1[256 * H + j];
    for (int i = 0; i < H; i++)
        acc += rel[r * H + i] * W1[(H + i) * H + j];
    g_R2x[r * H + j] = acc;
}

// ---------------- weight image: BT[n][k] = W[k][n], fp16 -------------------
__global__ void k_prepw(const float* __restrict__ Wk, const float* __restrict__ Wv) {
    int n = blockIdx.x, k = threadIdx.x;
    float w = (n < H) ? Wk[k * H + n] : Wv[k * H + (n - H)];
    unsigned kb = (unsigned)k * 2u;
    unsigned phys = (unsigned)n * 256u + (kb ^ ((unsigned)(n & 7) << 4));
    *(__half*)((char*)g_B + phys) = __float2half_rn(w);
}

// ---------------- node precompute: Q = x@Wq+bq, S1 = x@W1[:128] ------------
__global__ void __launch_bounds__(128) k_node(
    const float* __restrict__ x, const float* __restrict__ Wq,
    const float* __restrict__ bq, const float* __restrict__ W1, int N)
{
    __shared__ __align__(16) float xt[H * GPAD];
    int n0 = blockIdx.x * TEN;
    int j = threadIdx.x;
    int cnt = min(TEN, N - n0);
    for (int e = 0; e < TEN; e++)
        xt[j * GPAD + e] = (e < cnt) ? x[(size_t)(n0 + e) * H + j] : 0.f;
    __syncthreads();

    unsigned long long aq[TEN / 2], as_[TEN / 2];
#pragma unroll
    for (int i = 0; i < TEN / 2; i++) { aq[i] = 0ull; as_[i] = 0ull; }
    for (int kk = 0; kk < H; kk++) {
        float wq = Wq[kk * H + j];
        float w1 = W1[kk * H + j];
        unsigned long long wq2, w12;
        DUP2(wq2, wq);
        DUP2(w12, w1);
        const ulonglong2* gp = (const ulonglong2*)(&xt[kk * GPAD]);
#pragma unroll
        for (int q4 = 0; q4 < TEN / 4; q4++) {
            ulonglong2 gg = gp[q4];
            F2MA(aq[q4 * 2],      gg.x, wq2);
            F2MA(aq[q4 * 2 + 1],  gg.y, wq2);
            F2MA(as_[q4 * 2],     gg.x, w12);
            F2MA(as_[q4 * 2 + 1], gg.y, w12);
        }
    }
    float bqj = bq[j];
    for (int e = 0; e < cnt; e++) {
        float vq = (e & 1) ? __uint_as_float((unsigned)(aq[e >> 1] >> 32))
                           : __uint_as_float((unsigned)(aq[e >> 1] & 0xFFFFFFFFull));
        float vs = (e & 1) ? __uint_as_float((unsigned)(as_[e >> 1] >> 32))
                           : __uint_as_float((unsigned)(as_[e >> 1] & 0xFFFFFFFFull));
        g_Q [(n0 + e) * H + j] = vq + bqj;
        g_S1[(n0 + e) * H + j] = vs;
    }
}

// ---------------- persistent fused edge kernel (fp16 mma.sync, 2 CTA/SM) ---
__global__ void __launch_bounds__(NT, 2) k_edge_mma(
    const float* __restrict__ x, const float* __restrict__ ts,
    const int* __restrict__ src, const int* __restrict__ dst, const int* __restrict__ et,
    const float* __restrict__ etime, const float* __restrict__ rel,
    const float* __restrict__ bk, const float* __restrict__ bv,
    const float* __restrict__ b1, const float* __restrict__ W2,
    const float* __restrict__ b2, const float* __restrict__ tcp,
    float* __restrict__ out, int E, int ntiles)
{
    extern __shared__ __align__(1024) char smc[];
    uint32_t smb = s2u(smc);
    int tid = threadIdx.x, wid = tid >> 5, lane = tid & 31;

    float* bk_s  = (float*)(smc + OFF_BK);
    float* bv_s  = (float*)(smc + OFF_BV);
    float* b1_s  = (float*)(smc + OFF_B1);
    float* w2_s  = (float*)(smc + OFF_W2);
    int*   dst_s = (int*)  (smc + OFF_DST);
    int*   src_s = (int*)  (smc + OFF_SRC);
    int*   et_s  = (int*)  (smc + OFF_ET);
    float* tm_s  = (float*)(smc + OFF_TM);
    float* ss_s  = (float*)(smc + OFF_SS);
    float* w_sm  = (float*)(smc + OFF_WS);

    // stage B image into smem once per CTA
    {
        float4* d0 = (float4*)(smc + OFF_B);
        const float4* s0 = (const float4*)g_B;
        for (int i = tid; i < 4096; i += NT) d0[i] = s0[i];
    }
    if (tid < H) { bk_s[tid] = bk[tid]; bv_s[tid] = bv[tid]; b1_s[tid] = b1[tid]; w2_s[tid] = W2[tid]; }
    __syncthreads();

    float inv_tc = 1.f / (fabsf(tcp[0]) + 1e-9f);
    float b2v = b2[0];

    // ---- per-warp GEMM tiling: m64 x n32, 8 warps across n256 ----
    int n0 = wid * 32;
    bool isK = (n0 < 128);

    // ldmatrix A lane addressing
    int ra = lane & 7, ha = (lane >> 3) & 1, kh = lane >> 4;
    uint32_t aXor = (uint32_t)ra << 4;
    uint32_t aKh = (uint32_t)(kh * 16);
    uint32_t aRowBase = smb + OFF_A + (uint32_t)(ha * 8 + ra) * 256u;

    // ldmatrix B lane addressing
    int qb = lane >> 3, rb = lane & 7;
    uint32_t bXor = (uint32_t)rb << 4;
    uint32_t bKh = (uint32_t)((qb & 1) * 16);
    uint32_t bRow0 = smb + OFF_B + (uint32_t)(n0 + (qb >> 1) * 8 + rb) * 256u;
    uint32_t bRow1 = bRow0 + 16u * 256u;

    int r4 = lane >> 2, c2 = (lane & 3) * 2;

    // gather mapping: 4 threads per edge
    int ge = tid >> 2, gq = tid & 3;

    for (int t = blockIdx.x; t < ntiles; t += gridDim.x) {
        int e0 = t * TILE_E;
        int cnt = min(TILE_E, E - e0);

        // ---- phase 0: edge meta + time gate ----
        if (tid < TILE_E) {
            float tm = 0.f;
            if (tid < cnt) {
                int ee = e0 + tid;
                int d = dst[ee];
                src_s[tid] = src[ee]; dst_s[tid] = d; et_s[tid] = et[ee];
                float dt = (ts[d] - etime[ee]) * inv_tc;
                tm = 1.f / (1.f + expf(-dt));
            } else { src_s[tid] = 0; dst_s[tid] = 0; et_s[tid] = 0; }
            tm_s[tid] = tm;
        }
        __syncthreads();

        // ---- phase 1: gather g = x[src]*rel[et] -> fp16 A tile + dw ----
        {
            int sn = src_s[ge], rr = et_s[ge];
            float tme = tm_s[ge];
            const float4* xp  = (const float4*)(x     + (size_t)sn * H) + gq * 8;
            const float4* rp  = (const float4*)(rel   + (size_t)rr * H) + gq * 8;
            const float4* sp  = (const float4*)(g_S1  + (size_t)sn * H) + gq * 8;
            const float4* r2p = (const float4*)(g_R2x + (size_t)rr * H) + gq * 8;
            char* Ah = smc + OFF_A + ge * 256;
            unsigned xr = (unsigned)(ge & 7) << 4;
            float hacc = 0.f;
#pragma unroll
            for (int i = 0; i < 8; i++) {
                float4 xv = __ldg(xp + i), rv = __ldg(rp + i);
                float4 s1 = __ldg(sp + i), r2 = __ldg(r2p + i);
                int col = gq * 32 + i * 4;
                float4 b14 = *(const float4*)(b1_s + col);
                float4 w24 = *(const float4*)(w2_s + col);
                float g0 = xv.x * rv.x, g1 = xv.y * rv.y, g2 = xv.z * rv.z, g3 = xv.w * rv.w;
                hacc += fmaxf(fmaf(tme, r2.x, s1.x + b14.x), 0.f) * w24.x;
                hacc += fmaxf(fmaf(tme, r2.y, s1.y + b14.y), 0.f) * w24.y;
                hacc += fmaxf(fmaf(tme, r2.z, s1.z + b14.z), 0.f) * w24.z;
                hacc += fmaxf(fmaf(tme, r2.w, s1.w + b14.w), 0.f) * w24.w;
                __half2 h01 = __floats2half2_rn(g0, g1);
                __half2 h23 = __floats2half2_rn(g2, g3);
                unsigned kb = (unsigned)(gq * 64 + i * 8);
                uint2 uh; uh.x = *(unsigned*)&h01; uh.y = *(unsigned*)&h23;
                *(uint2*)(Ah + (kb ^ xr)) = uh;
            }
            // dw = sigmoid(h.W2+b2) reduced across the 4 lanes of this edge
            hacc += __shfl_xor_sync(0xFFFFFFFFu, hacc, 1);
            hacc += __shfl_xor_sync(0xFFFFFFFFu, hacc, 2);
            if ((tid & 3) == 0) {
                float dw = 1.f / (1.f + expf(-(hacc + b2v)));
                ss_s[ge] = tm_s[ge] * dw;
            }
        }
        __syncthreads();

        // ---- phase 2: GEMM 64x256x128 fp16, m64n32 per warp ----
        float acc[4][4][4];
#pragma unroll
        for (int mt = 0; mt < 4; mt++)
#pragma unroll
            for (int ng = 0; ng < 4; ng++)
#pragma unroll
                for (int i = 0; i < 4; i++) acc[mt][ng][i] = 0.f;

        for (int ks = 0; ks < 8; ks++) {
            uint32_t kbB = ((uint32_t)(ks * 32) + bKh) ^ bXor;
            uint32_t bh[8];
            ldsm4(bh + 0, bRow0 + kbB);
            ldsm4(bh + 4, bRow1 + kbB);
            uint32_t kbA = ((uint32_t)(ks * 32) + aKh) ^ aXor;
#pragma unroll
            for (int mt = 0; mt < 4; mt++) {
                uint32_t ah[4];
                ldsm4(ah, aRowBase + (uint32_t)(mt * 16) * 256u + kbA);
#pragma unroll
                for (int ng = 0; ng < 4; ng++)
                    mma16816(acc[mt][ng], ah, bh + ng * 2);
            }
        }
        __syncthreads();   // A tile no longer needed; KV buf aliases it

        // ---- stage K accums to smem (swizzled rows of 512B) ----
        if (isK) {
#pragma unroll
            for (int mt = 0; mt < 4; mt++) {
#pragma unroll
                for (int ng = 0; ng < 4; ng++) {
                    int ee = mt * 16 + r4;
                    unsigned jb = (unsigned)((n0 + ng * 8 + c2) * 4);
                    char* base = smc + OFF_KV;
                    *(float2*)(base + ee * 512 + (jb ^ ((unsigned)(ee & 31) << 4))) =
                        make_float2(acc[mt][ng][0], acc[mt][ng][1]);
                    int ee2 = ee + 8;
                    *(float2*)(base + ee2 * 512 + (jb ^ ((unsigned)(ee2 & 31) << 4))) =
                        make_float2(acc[mt][ng][2], acc[mt][ng][3]);
                }
            }
        }
        __syncthreads();

        // ---- score phase: thread covers 32 cols (2 heads) of one edge ----
        {
            int qq = wid & 3;
            int e = (wid >> 2) * 32 + lane;
            int d2 = dst_s[e];
            float sce = ss_s[e];
            bool valid = (e < cnt);
            const float* qrow = g_Q + (size_t)d2 * H;
            char* kbase = smc + OFF_KV + e * 512;
            unsigned xr = (unsigned)(e & 31) << 4;
            float s0 = 0.f, s1 = 0.f;
#pragma unroll
            for (int i = 0; i < 8; i++) {
                unsigned jb = (unsigned)(qq * 128 + i * 16);
                float4 kr = *(float4*)(kbase + (jb ^ xr));
                int j = qq * 32 + i * 4;
                float4 q4 = __ldg((const float4*)(qrow + j));
                float k0 = fmaf(kr.x, sce, bk_s[j + 0]);
                float k1 = fmaf(kr.y, sce, bk_s[j + 1]);
                float k2 = fmaf(kr.z, sce, bk_s[j + 2]);
                float k3 = fmaf(kr.w, sce, bk_s[j + 3]);
                float dp = q4.x * k0 + q4.y * k1 + q4.z * k2 + q4.w * k3;
                if (i < 4) s0 += dp; else s1 += dp;
            }
            float w0 = expf(s0 * 0.25f);
            float w1 = expf(s1 * 0.25f);
            w_sm[e * 8 + 2 * qq + 0] = w0;
            w_sm[e * 8 + 2 * qq + 1] = w1;
            if (valid) {
                float* dp = &g_denom[(size_t)d2 * NHEAD + 2 * qq];
                asm volatile("red.global.add.v2.f32 [%0], {%1,%2};"
                             :: "l"(dp), "f"(w0), "f"(w1) : "memory");
            }
        }
        __syncthreads();

        // ---- stage V accums to smem (same buffer) ----
        if (!isK) {
#pragma unroll
            for (int mt = 0; mt < 4; mt++) {
#pragma unroll
                for (int ng = 0; ng < 4; ng++) {
                    int ee = mt * 16 + r4;
                    unsigned jb = (unsigned)((n0 - 128 + ng * 8 + c2) * 4);
                    char* base = smc + OFF_KV;
                    *(float2*)(base + ee * 512 + (jb ^ ((unsigned)(ee & 31) << 4))) =
                        make_float2(acc[mt][ng][0], acc[mt][ng][1]);
                    int ee2 = ee + 8;
                    *(float2*)(base + ee2 * 512 + (jb ^ ((unsigned)(ee2 & 31) << 4))) =
                        make_float2(acc[mt][ng][2], acc[mt][ng][3]);
                }
            }
        }
        __syncthreads();

        // ---- V scatter phase ----
        {
            int qq = wid & 3;
            int e = (wid >> 2) * 32 + lane;
            int d2 = dst_s[e];
            float sce = ss_s[e];
            bool valid = (e < cnt);
            char* vbase = smc + OFF_KV + e * 512;
            unsigned xr = (unsigned)(e & 31) << 4;
            float* orow = out + (size_t)d2 * H;
#pragma unroll
            for (int i = 0; i < 8; i++) {
                unsigned jb = (unsigned)(qq * 128 + i * 16);
                float4 vr = *(float4*)(vbase + (jb ^ xr));
                int j = qq * 32 + i * 4;
                float ww = w_sm[e * 8 + 2 * qq + (i >> 2)];
                float v0 = fmaf(vr.x, sce, bv_s[j + 0]) * ww;
                float v1 = fmaf(vr.y, sce, bv_s[j + 1]) * ww;
                float v2 = fmaf(vr.z, sce, bv_s[j + 2]) * ww;
                float v3 = fmaf(vr.w, sce, bv_s[j + 3]) * ww;
                if (valid)
                    asm volatile("red.global.add.v4.f32 [%0], {%1,%2,%3,%4};"
                                 :: "l"(orow + j), "f"(v0), "f"(v1), "f"(v2), "f"(v3) : "memory");
            }
        }
        __syncthreads();
    }
}

// ---------------- normalize ------------------------------------------------
__global__ void k_norm(float* __restrict__ out, int N)
{
    int idx = blockIdx.x * blockDim.x + threadIdx.x;
    if (idx >= N * H) return;
    int n = idx >> 7, jj = idx & (H - 1);
    float dnm = g_denom[n * NHEAD + (jj >> 4)];
    float v = out[idx];
    out[idx] = (dnm > 0.f) ? v / dnm : 0.f;
}

// ---------------- launch ---------------------------------------------------
extern "C" void kernel_launch(void* const* d_in, const int* in_sizes, int n_in,
                              void* d_out, int out_size)
{
    const float* x     = (const float*)d_in[0];
    const float* ts    = (const float*)d_in[1];
    const int*   src   = (const int*)  d_in[2];
    const int*   dst   = (const int*)  d_in[3];
    const int*   etyp  = (const int*)  d_in[4];
    const float* etime = (const float*)d_in[5];
    const float* rel   = (const float*)d_in[6];
    const float* Wq    = (const float*)d_in[7];
    const float* bq    = (const float*)d_in[8];
    const float* Wk    = (const float*)d_in[9];
    const float* bk    = (const float*)d_in[10];
    const float* Wv    = (const float*)d_in[11];
    const float* bv    = (const float*)d_in[12];
    const float* W1    = (const float*)d_in[13];
    const float* b1    = (const float*)d_in[14];
    const float* W2    = (const float*)d_in[15];
    const float* b2    = (const float*)d_in[16];
    const float* tcp   = (const float*)d_in[17];

    int N    = in_sizes[0] / H;
    int E    = in_sizes[2];
    int NREL = in_sizes[6] / H;
    float* out = (float*)d_out;
    int ntiles = (E + TILE_E - 1) / TILE_E;

    static int smem_set = 0;
    if (!smem_set) {
        cudaFuncSetAttribute(k_edge_mma, cudaFuncAttributeMaxDynamicSharedMemorySize, SMEM_EDGE);
        smem_set = 1;
    }

    k_init <<<2048, 256>>>(out, N, out_size);
    k_rel  <<<NREL, H>>>(rel, W1);
    k_prepw<<<256, H>>>(Wk, Wv);
    k_node <<<(N + TEN - 1) / TEN, H>>>(x, Wq, bq, W1, N);
    k_edge_mma<<<296, NT, SMEM_EDGE>>>(x, ts, src, dst, etyp, etime, rel,
                                       bk, bv, b1, W2, b2, tcp, out, E, ntiles);
    k_norm <<<(N * H + 255) / 256, 256>>>(out, N);
}

// round 9
// speedup vs baseline: 1.2364x; 1.2364x over previous
#include <cuda_runtime.h>
#include <cuda_fp16.h>
#include <cstdint>

#define H       128
#define NHEAD   8
#define N_MAX   50000
#define NRELMX  64
#define TEN     32
#define GPAD    36
#define TILE_E  128
#define NT      512

// ---------------- global scratch -------------------------------------------
__device__ float g_Q  [N_MAX * H];
__device__ float g_S1 [N_MAX * H];
__device__ float g_R2x[NRELMX * H];
__device__ float g_denom[N_MAX * NHEAD];
__device__ __half g_B[256 * H];   // [n][k] fp16, 256B rows, XOR-16B swizzle

// ---------------- smem layout ----------------------------------------------
#define OFF_B     0        // 65536
#define OFF_A     65536    // 32768 (fp16 A tile, 128 x 256B)
#define OFF_B1    98304    // 512
#define OFF_W2    98816    // 512
#define OFF_DST   99328    // 512
#define OFF_SS    99840    // 512
#define OFF_WS    100352   // w_sm[128][8] = 4096
#define SMEM_EDGE 104448

// ---------------- helpers --------------------------------------------------
__device__ __forceinline__ uint32_t s2u(const void* p) {
    uint32_t a;
    asm("{ .reg .u64 t; cvta.to.shared.u64 t, %1; cvt.u32.u64 %0, t; }" : "=r"(a) : "l"(p));
    return a;
}
__device__ __forceinline__ void ldsm4(uint32_t* r, uint32_t addr) {
    asm volatile("ldmatrix.sync.aligned.m8n8.x4.shared.b16 {%0,%1,%2,%3}, [%4];"
                 : "=r"(r[0]), "=r"(r[1]), "=r"(r[2]), "=r"(r[3]) : "r"(addr));
}
__device__ __forceinline__ void mma16816(float* c, const uint32_t* a, const uint32_t* b) {
    asm volatile(
        "mma.sync.aligned.m16n8k16.row.col.f32.f16.f16.f32 "
        "{%0,%1,%2,%3}, {%4,%5,%6,%7}, {%8,%9}, {%0,%1,%2,%3};"
        : "+f"(c[0]), "+f"(c[1]), "+f"(c[2]), "+f"(c[3])
        : "r"(a[0]), "r"(a[1]), "r"(a[2]), "r"(a[3]), "r"(b[0]), "r"(b[1]));
}
#define DUP2(d, s) asm("mov.b64 %0, {%1,%1};" : "=l"(d) : "f"(s))
#define F2MA(acc, a, b) asm("fma.rn.f32x2 %0, %1, %2, %0;" : "+l"(acc) : "l"(a), "l"(b))
#define REDV2(p, a, b) asm volatile("red.global.add.v2.f32 [%0], {%1,%2};" :: "l"(p), "f"(a), "f"(b) : "memory")

// ---------------- init -----------------------------------------------------
__global__ void k_init(float* __restrict__ out, int N, int outElems) {
    int i = blockIdx.x * blockDim.x + threadIdx.x;
    int stride = gridDim.x * blockDim.x;
    for (int idx = i; idx < outElems; idx += stride) out[idx] = 0.f;
    for (int idx = i; idx < N * NHEAD; idx += stride) g_denom[idx] = 0.f;
}

// ---------------- R2x[r] = rel[r] @ W1[128:256] + W1[256] ------------------
__global__ void k_rel(const float* __restrict__ rel, const float* __restrict__ W1) {
    int r = blockIdx.x, j = threadIdx.x;
    float acc = W1[256 * H + j];
    for (int i = 0; i < H; i++)
        acc += rel[r * H + i] * W1[(H + i) * H + j];
    g_R2x[r * H + j] = acc;
}

// ---------------- weight image: BT[n][k] = W[k][n], fp16 -------------------
__global__ void k_prepw(const float* __restrict__ Wk, const float* __restrict__ Wv) {
    int n = blockIdx.x, k = threadIdx.x;
    float w = (n < H) ? Wk[k * H + n] : Wv[k * H + (n - H)];
    unsigned kb = (unsigned)k * 2u;
    unsigned phys = (unsigned)n * 256u + (kb ^ ((unsigned)(n & 7) << 4));
    *(__half*)((char*)g_B + phys) = __float2half_rn(w);
}

// ---------------- node precompute: Q = x@Wq+bq, S1 = x@W1[:128] ------------
__global__ void __launch_bounds__(128) k_node(
    const float* __restrict__ x, const float* __restrict__ Wq,
    const float* __restrict__ bq, const float* __restrict__ W1, int N)
{
    __shared__ __align__(16) float xt[H * GPAD];
    int n0 = blockIdx.x * TEN;
    int j = threadIdx.x;
    int cnt = min(TEN, N - n0);
    for (int e = 0; e < TEN; e++)
        xt[j * GPAD + e] = (e < cnt) ? x[(size_t)(n0 + e) * H + j] : 0.f;
    __syncthreads();

    unsigned long long aq[TEN / 2], as_[TEN / 2];
#pragma unroll
    for (int i = 0; i < TEN / 2; i++) { aq[i] = 0ull; as_[i] = 0ull; }
    for (int kk = 0; kk < H; kk++) {
        float wq = Wq[kk * H + j];
        float w1 = W1[kk * H + j];
        unsigned long long wq2, w12;
        DUP2(wq2, wq);
        DUP2(w12, w1);
        const ulonglong2* gp = (const ulonglong2*)(&xt[kk * GPAD]);
#pragma unroll
        for (int q4 = 0; q4 < TEN / 4; q4++) {
            ulonglong2 gg = gp[q4];
            F2MA(aq[q4 * 2],      gg.x, wq2);
            F2MA(aq[q4 * 2 + 1],  gg.y, wq2);
            F2MA(as_[q4 * 2],     gg.x, w12);
            F2MA(as_[q4 * 2 + 1], gg.y, w12);
        }
    }
    float bqj = bq[j];
    for (int e = 0; e < cnt; e++) {
        float vq = (e & 1) ? __uint_as_float((unsigned)(aq[e >> 1] >> 32))
                           : __uint_as_float((unsigned)(aq[e >> 1] & 0xFFFFFFFFull));
        float vs = (e & 1) ? __uint_as_float((unsigned)(as_[e >> 1] >> 32))
                           : __uint_as_float((unsigned)(as_[e >> 1] & 0xFFFFFFFFull));
        g_Q [(n0 + e) * H + j] = vq + bqj;
        g_S1[(n0 + e) * H + j] = vs;
    }
}

// ---------------- persistent fused edge kernel (fp16 mma, reg epilogue) ----
__global__ void __launch_bounds__(NT, 1) k_edge_mma(
    const float* __restrict__ x, const float* __restrict__ ts,
    const int* __restrict__ src, const int* __restrict__ dst, const int* __restrict__ et,
    const float* __restrict__ etime, const float* __restrict__ rel,
    const float* __restrict__ bk, const float* __restrict__ bv,
    const float* __restrict__ b1, const float* __restrict__ W2,
    const float* __restrict__ b2, const float* __restrict__ tcp,
    float* __restrict__ out, int E, int ntiles)
{
    extern __shared__ __align__(1024) char smc[];
    uint32_t smb = s2u(smc);
    int tid = threadIdx.x, wid = tid >> 5, lane = tid & 31;

    float* b1_s  = (float*)(smc + OFF_B1);
    float* w2_s  = (float*)(smc + OFF_W2);
    int*   dst_s = (int*)  (smc + OFF_DST);
    float* ss_s  = (float*)(smc + OFF_SS);
    float* w_sm  = (float*)(smc + OFF_WS);

    // stage B image into smem once per CTA
    {
        float4* d0 = (float4*)(smc + OFF_B);
        const float4* s0 = (const float4*)g_B;
        for (int i = tid; i < 4096; i += NT) d0[i] = s0[i];
    }
    if (tid < H) { b1_s[tid] = b1[tid]; w2_s[tid] = W2[tid]; }
    __syncthreads();

    float inv_tc = 1.f / (fabsf(tcp[0]) + 1e-9f);
    float b2v = b2[0];

    // ---- per-warp GEMM tiling: m64 x n32, 2x8 warp grid ----
    int warp_row = wid & 1;
    int warp_col = wid >> 1;
    int n0 = warp_col * 32;
    bool isK = (n0 < 128);

    // ldmatrix A lane addressing
    int ra = lane & 7, ha = (lane >> 3) & 1, kh = lane >> 4;
    uint32_t aXor = (uint32_t)ra << 4;
    uint32_t aKh = (uint32_t)(kh * 16);
    uint32_t aRowBase = smb + OFF_A + (uint32_t)(warp_row * 64 + ha * 8 + ra) * 256u;

    // ldmatrix B lane addressing
    int qb = lane >> 3, rb = lane & 7;
    uint32_t bXor = (uint32_t)rb << 4;
    uint32_t bKh = (uint32_t)((qb & 1) * 16);
    uint32_t bRow0 = smb + OFF_B + (uint32_t)(n0 + (qb >> 1) * 8 + rb) * 256u;
    uint32_t bRow1 = bRow0 + 16u * 256u;

    int r4 = lane >> 2, c2 = (lane & 3) * 2;

    // gather mapping: 4 threads per edge
    int ge = tid >> 2, gq = tid & 3;

    // epilogue bias hoist (per-thread cols)
    float bias_l[8];
    {
        const float* bb = isK ? bk : bv;
        int cb = (isK ? n0 : n0 - 128) + c2;
#pragma unroll
        for (int ng = 0; ng < 4; ng++) {
            bias_l[ng * 2 + 0] = __ldg(bb + cb + ng * 8);
            bias_l[ng * 2 + 1] = __ldg(bb + cb + ng * 8 + 1);
        }
    }

    for (int t = blockIdx.x; t < ntiles; t += gridDim.x) {
        int e0 = t * TILE_E;
        int cnt = min(TILE_E, E - e0);

        // ---- phase 1: meta (quad leader) + gather -> fp16 A tile + dw ----
        {
            int sn = 0, rr = 0;
            float tme = 0.f;
            if (gq == 0) {
                if (ge < cnt) {
                    int ee = e0 + ge;
                    int d = dst[ee];
                    sn = src[ee];
                    rr = et[ee];
                    float dt = (ts[d] - etime[ee]) * inv_tc;
                    tme = 1.f / (1.f + expf(-dt));
                    dst_s[ge] = d;
                } else {
                    dst_s[ge] = 0;
                }
            }
            int ldr = lane & ~3;
            sn  = __shfl_sync(0xFFFFFFFFu, sn,  ldr);
            rr  = __shfl_sync(0xFFFFFFFFu, rr,  ldr);
            tme = __shfl_sync(0xFFFFFFFFu, tme, ldr);

            const float4* xp  = (const float4*)(x     + (size_t)sn * H) + gq * 8;
            const float4* rp  = (const float4*)(rel   + (size_t)rr * H) + gq * 8;
            const float4* sp  = (const float4*)(g_S1  + (size_t)sn * H) + gq * 8;
            const float4* r2p = (const float4*)(g_R2x + (size_t)rr * H) + gq * 8;
            char* Ah = smc + OFF_A + ge * 256;
            unsigned xr = (unsigned)(ge & 7) << 4;
            float hacc = 0.f;
#pragma unroll
            for (int i = 0; i < 8; i++) {
                float4 xv = __ldg(xp + i), rv = __ldg(rp + i);
                float4 s1 = __ldg(sp + i), r2 = __ldg(r2p + i);
                int col = gq * 32 + i * 4;
                float4 b14 = *(const float4*)(b1_s + col);
                float4 w24 = *(const float4*)(w2_s + col);
                float g0 = xv.x * rv.x, g1 = xv.y * rv.y, g2 = xv.z * rv.z, g3 = xv.w * rv.w;
                hacc += fmaxf(fmaf(tme, r2.x, s1.x + b14.x), 0.f) * w24.x;
                hacc += fmaxf(fmaf(tme, r2.y, s1.y + b14.y), 0.f) * w24.y;
                hacc += fmaxf(fmaf(tme, r2.z, s1.z + b14.z), 0.f) * w24.z;
                hacc += fmaxf(fmaf(tme, r2.w, s1.w + b14.w), 0.f) * w24.w;
                __half2 h01 = __floats2half2_rn(g0, g1);
                __half2 h23 = __floats2half2_rn(g2, g3);
                unsigned kb = (unsigned)(gq * 64 + i * 8);
                uint2 uh; uh.x = *(unsigned*)&h01; uh.y = *(unsigned*)&h23;
                *(uint2*)(Ah + (kb ^ xr)) = uh;
            }
            // dw = sigmoid(h.W2+b2) reduced across the 4 lanes of this edge
            hacc += __shfl_xor_sync(0xFFFFFFFFu, hacc, 1);
            hacc += __shfl_xor_sync(0xFFFFFFFFu, hacc, 2);
            if (gq == 0) {
                float dw = 1.f / (1.f + expf(-(hacc + b2v)));
                ss_s[ge] = tme * dw;
            }
        }
        __syncthreads();

        // ---- phase 2: GEMM 128x256x128 fp16, m64n32 per warp ----
        float acc[4][4][4];
#pragma unroll
        for (int mt = 0; mt < 4; mt++)
#pragma unroll
            for (int ng = 0; ng < 4; ng++)
#pragma unroll
                for (int i = 0; i < 4; i++) acc[mt][ng][i] = 0.f;

        for (int ks = 0; ks < 8; ks++) {
            uint32_t kbB = ((uint32_t)(ks * 32) + bKh) ^ bXor;
            uint32_t bh[8];
            ldsm4(bh + 0, bRow0 + kbB);
            ldsm4(bh + 4, bRow1 + kbB);
            uint32_t kbA = ((uint32_t)(ks * 32) + aKh) ^ aXor;
#pragma unroll
            for (int mt = 0; mt < 4; mt++) {
                uint32_t ah[4];
                ldsm4(ah, aRowBase + (uint32_t)(mt * 16) * 256u + kbA);
#pragma unroll
                for (int ng = 0; ng < 4; ng++)
                    mma16816(acc[mt][ng], ah, bh + ng * 2);
            }
        }

        // ---- phase 3: K-warps score epilogue (register-resident) ----
        if (isK) {
#pragma unroll
            for (int mt = 0; mt < 4; mt++) {
#pragma unroll
                for (int hf = 0; hf < 2; hf++) {
                    int e = warp_row * 64 + mt * 16 + hf * 8 + r4;
                    int d2 = dst_s[e];
                    float sce = ss_s[e];
                    const float* qrow = g_Q + (size_t)d2 * H + n0 + c2;
                    float sA = 0.f, sB = 0.f;
#pragma unroll
                    for (int ng = 0; ng < 4; ng++) {
                        float k0 = fmaf(acc[mt][ng][hf * 2 + 0], sce, bias_l[ng * 2 + 0]);
                        float k1 = fmaf(acc[mt][ng][hf * 2 + 1], sce, bias_l[ng * 2 + 1]);
                        float2 q2 = __ldg((const float2*)(qrow + ng * 8));
                        float dp = q2.x * k0 + q2.y * k1;
                        if (ng < 2) sA += dp; else sB += dp;
                    }
                    sA += __shfl_xor_sync(0xFFFFFFFFu, sA, 1);
                    sA += __shfl_xor_sync(0xFFFFFFFFu, sA, 2);
                    sB += __shfl_xor_sync(0xFFFFFFFFu, sB, 1);
                    sB += __shfl_xor_sync(0xFFFFFFFFu, sB, 2);
                    if (c2 == 0) {
                        float w0 = expf(sA * 0.25f);
                        float w1 = expf(sB * 0.25f);
                        w_sm[e * 8 + warp_col * 2 + 0] = w0;
                        w_sm[e * 8 + warp_col * 2 + 1] = w1;
                        if (e < cnt) {
                            float* dp2 = &g_denom[(size_t)d2 * NHEAD + warp_col * 2];
                            REDV2(dp2, w0, w1);
                        }
                    }
                }
            }
        }
        __syncthreads();

        // ---- phase 4: V-warps weighted scatter (register-resident) ----
        if (!isK) {
            int vb = n0 - 128;
#pragma unroll
            for (int mt = 0; mt < 4; mt++) {
#pragma unroll
                for (int hf = 0; hf < 2; hf++) {
                    int e = warp_row * 64 + mt * 16 + hf * 8 + r4;
                    if (e < cnt) {
                        int d2 = dst_s[e];
                        float sce = ss_s[e];
                        float* orow = out + (size_t)d2 * H + vb + c2;
#pragma unroll
                        for (int ng = 0; ng < 4; ng++) {
                            float ww = w_sm[e * 8 + ((vb + ng * 8) >> 4)];
                            float v0 = fmaf(acc[mt][ng][hf * 2 + 0], sce, bias_l[ng * 2 + 0]) * ww;
                            float v1 = fmaf(acc[mt][ng][hf * 2 + 1], sce, bias_l[ng * 2 + 1]) * ww;
                            REDV2(orow + ng * 8, v0, v1);
                        }
                    }
                }
            }
        }
        __syncthreads();
    }
}

// ---------------- normalize ------------------------------------------------
__global__ void k_norm(float* __restrict__ out, int N)
{
    int idx = blockIdx.x * blockDim.x + threadIdx.x;
    if (idx >= N * H) return;
    int n = idx >> 7, jj = idx & (H - 1);
    float dnm = g_denom[n * NHEAD + (jj >> 4)];
    float v = out[idx];
    out[idx] = (dnm > 0.f) ? v / dnm : 0.f;
}

// ---------------- launch ---------------------------------------------------
extern "C" void kernel_launch(void* const* d_in, const int* in_sizes, int n_in,
                              void* d_out, int out_size)
{
    const float* x     = (const float*)d_in[0];
    const float* ts    = (const float*)d_in[1];
    const int*   src   = (const int*)  d_in[2];
    const int*   dst   = (const int*)  d_in[3];
    const int*   etyp  = (const int*)  d_in[4];
    const float* etime = (const float*)d_in[5];
    const float* rel   = (const float*)d_in[6];
    const float* Wq    = (const float*)d_in[7];
    const float* bq    = (const float*)d_in[8];
    const float* Wk    = (const float*)d_in[9];
    const float* bk    = (const float*)d_in[10];
    const float* Wv    = (const float*)d_in[11];
    const float* bv    = (const float*)d_in[12];
    const float* W1    = (const float*)d_in[13];
    const float* b1    = (const float*)d_in[14];
    const float* W2    = (const float*)d_in[15];
    const float* b2    = (const float*)d_in[16];
    const float* tcp   = (const float*)d_in[17];

    int N    = in_sizes[0] / H;
    int E    = in_sizes[2];
    int NREL = in_sizes[6] / H;
    float* out = (float*)d_out;
    int ntiles = (E + TILE_E - 1) / TILE_E;

    static int smem_set = 0;
    if (!smem_set) {
        cudaFuncSetAttribute(k_edge_mma, cudaFuncAttributeMaxDynamicSharedMemorySize, SMEM_EDGE);
        smem_set = 1;
    }

    k_init <<<2048, 256>>>(out, N, out_size);
    k_rel  <<<NREL, H>>>(rel, W1);
    k_prepw<<<256, H>>>(Wk, Wv);
    k_node <<<(N + TEN - 1) / TEN, H>>>(x, Wq, bq, W1, N);
    k_edge_mma<<<148, NT, SMEM_EDGE>>>(x, ts, src, dst, etyp, etime, rel,
                                       bk, bv, b1, W2, b2, tcp, out, E, ntiles);
    k_norm <<<(N * H + 255) / 256, 256>>>(out, N);
}

// round 10
// speedup vs baseline: 1.2381x; 1.0014x over previous
#include <cuda_runtime.h>
#include <cuda_fp16.h>
#include <cstdint>

#define H       128
#define NHEAD   8
#define N_MAX   50000
#define NRELMX  64
#define TEN     32
#define GPAD    36
#define TILE_E  128
#define NT      512

// ---------------- global scratch -------------------------------------------
__device__ float g_Q  [N_MAX * H];
__device__ float g_S1 [N_MAX * H];
__device__ float g_R2x[NRELMX * H];
__device__ float g_denom[N_MAX * NHEAD];
__device__ __half g_B[256 * H];   // [n][k] fp16, 256B rows, XOR-16B swizzle

// ---------------- smem layout ----------------------------------------------
#define OFF_B     0        // 65536
#define OFF_A0    65536    // 32768
#define OFF_A1    98304    // 32768
#define OFF_B1    131072   // 512
#define OFF_W2    131584   // 512
#define OFF_DST0  132096   // 512
#define OFF_DST1  132608   // 512
#define OFF_SS0   133120   // 512
#define OFF_SS1   133632   // 512
#define OFF_BKs   134144   // 512
#define OFF_BVs   134656   // 512
#define OFF_WS    135168   // 4096
#define SMEM_EDGE 139264

// ---------------- helpers --------------------------------------------------
__device__ __forceinline__ uint32_t s2u(const void* p) {
    uint32_t a;
    asm("{ .reg .u64 t; cvta.to.shared.u64 t, %1; cvt.u32.u64 %0, t; }" : "=r"(a) : "l"(p));
    return a;
}
__device__ __forceinline__ void ldsm4(uint32_t* r, uint32_t addr) {
    asm volatile("ldmatrix.sync.aligned.m8n8.x4.shared.b16 {%0,%1,%2,%3}, [%4];"
                 : "=r"(r[0]), "=r"(r[1]), "=r"(r[2]), "=r"(r[3]) : "r"(addr));
}
__device__ __forceinline__ void mma16816(float* c, const uint32_t* a, const uint32_t* b) {
    asm volatile(
        "mma.sync.aligned.m16n8k16.row.col.f32.f16.f16.f32 "
        "{%0,%1,%2,%3}, {%4,%5,%6,%7}, {%8,%9}, {%0,%1,%2,%3};"
        : "+f"(c[0]), "+f"(c[1]), "+f"(c[2]), "+f"(c[3])
        : "r"(a[0]), "r"(a[1]), "r"(a[2]), "r"(a[3]), "r"(b[0]), "r"(b[1]));
}
#define DUP2(d, s) asm("mov.b64 %0, {%1,%1};" : "=l"(d) : "f"(s))
#define F2MA(acc, a, b) asm("fma.rn.f32x2 %0, %1, %2, %0;" : "+l"(acc) : "l"(a), "l"(b))
#define REDV2(p, a, b) asm volatile("red.global.add.v2.f32 [%0], {%1,%2};" :: "l"(p), "f"(a), "f"(b) : "memory")

// gather consume body: uses stx/strv/sts1/str2/hacc/gq/xr in scope
#define GBODY(i, Arow, tmev) do {                                             \
    int col_ = gq * 32 + (i) * 4;                                             \
    float4 b14 = *(const float4*)(b1_s + col_);                               \
    float4 w24 = *(const float4*)(w2_s + col_);                               \
    float g0 = stx.x * strv.x, g1 = stx.y * strv.y;                           \
    float g2 = stx.z * strv.z, g3 = stx.w * strv.w;                           \
    hacc += fmaxf(fmaf(tmev, str2.x, sts1.x + b14.x), 0.f) * w24.x;           \
    hacc += fmaxf(fmaf(tmev, str2.y, sts1.y + b14.y), 0.f) * w24.y;           \
    hacc += fmaxf(fmaf(tmev, str2.z, sts1.z + b14.z), 0.f) * w24.z;           \
    hacc += fmaxf(fmaf(tmev, str2.w, sts1.w + b14.w), 0.f) * w24.w;           \
    __half2 h01 = __floats2half2_rn(g0, g1);                                  \
    __half2 h23 = __floats2half2_rn(g2, g3);                                  \
    unsigned kb_ = (unsigned)(gq * 64 + (i) * 8);                             \
    uint2 uh_; uh_.x = *(unsigned*)&h01; uh_.y = *(unsigned*)&h23;            \
    *(uint2*)((Arow) + (kb_ ^ xr)) = uh_;                                     \
} while (0)

// ---------------- init -----------------------------------------------------
__global__ void k_init(float* __restrict__ out, int N, int outElems) {
    int i = blockIdx.x * blockDim.x + threadIdx.x;
    int stride = gridDim.x * blockDim.x;
    for (int idx = i; idx < outElems; idx += stride) out[idx] = 0.f;
    for (int idx = i; idx < N * NHEAD; idx += stride) g_denom[idx] = 0.f;
}

// ---------------- R2x[r] = rel[r] @ W1[128:256] + W1[256] ------------------
__global__ void k_rel(const float* __restrict__ rel, const float* __restrict__ W1) {
    int r = blockIdx.x, j = threadIdx.x;
    float acc = W1[256 * H + j];
    for (int i = 0; i < H; i++)
        acc += rel[r * H + i] * W1[(H + i) * H + j];
    g_R2x[r * H + j] = acc;
}

// ---------------- weight image: BT[n][k] = W[k][n], fp16 -------------------
__global__ void k_prepw(const float* __restrict__ Wk, const float* __restrict__ Wv) {
    int n = blockIdx.x, k = threadIdx.x;
    float w = (n < H) ? Wk[k * H + n] : Wv[k * H + (n - H)];
    unsigned kb = (unsigned)k * 2u;
    unsigned phys = (unsigned)n * 256u + (kb ^ ((unsigned)(n & 7) << 4));
    *(__half*)((char*)g_B + phys) = __float2half_rn(w);
}

// ---------------- node precompute: Q = x@Wq+bq, S1 = x@W1[:128] ------------
__global__ void __launch_bounds__(128) k_node(
    const float* __restrict__ x, const float* __restrict__ Wq,
    const float* __restrict__ bq, const float* __restrict__ W1, int N)
{
    __shared__ __align__(16) float xt[H * GPAD];
    int n0 = blockIdx.x * TEN;
    int j = threadIdx.x;
    int cnt = min(TEN, N - n0);
    for (int e = 0; e < TEN; e++)
        xt[j * GPAD + e] = (e < cnt) ? x[(size_t)(n0 + e) * H + j] : 0.f;
    __syncthreads();

    unsigned long long aq[TEN / 2], as_[TEN / 2];
#pragma unroll
    for (int i = 0; i < TEN / 2; i++) { aq[i] = 0ull; as_[i] = 0ull; }
    for (int kk = 0; kk < H; kk++) {
        float wq = Wq[kk * H + j];
        float w1 = W1[kk * H + j];
        unsigned long long wq2, w12;
        DUP2(wq2, wq);
        DUP2(w12, w1);
        const ulonglong2* gp = (const ulonglong2*)(&xt[kk * GPAD]);
#pragma unroll
        for (int q4 = 0; q4 < TEN / 4; q4++) {
            ulonglong2 gg = gp[q4];
            F2MA(aq[q4 * 2],      gg.x, wq2);
            F2MA(aq[q4 * 2 + 1],  gg.y, wq2);
            F2MA(as_[q4 * 2],     gg.x, w12);
            F2MA(as_[q4 * 2 + 1], gg.y, w12);
        }
    }
    float bqj = bq[j];
    for (int e = 0; e < cnt; e++) {
        float vq = (e & 1) ? __uint_as_float((unsigned)(aq[e >> 1] >> 32))
                           : __uint_as_float((unsigned)(aq[e >> 1] & 0xFFFFFFFFull));
        float vs = (e & 1) ? __uint_as_float((unsigned)(as_[e >> 1] >> 32))
                           : __uint_as_float((unsigned)(as_[e >> 1] & 0xFFFFFFFFull));
        g_Q [(n0 + e) * H + j] = vq + bqj;
        g_S1[(n0 + e) * H + j] = vs;
    }
}

// ---------------- persistent fused edge kernel (pipelined gather+MMA) ------
__global__ void __launch_bounds__(NT, 1) k_edge_mma(
    const float* __restrict__ x, const float* __restrict__ ts,
    const int* __restrict__ src, const int* __restrict__ dst, const int* __restrict__ et,
    const float* __restrict__ etime, const float* __restrict__ rel,
    const float* __restrict__ bk, const float* __restrict__ bv,
    const float* __restrict__ b1, const float* __restrict__ W2,
    const float* __restrict__ b2, const float* __restrict__ tcp,
    float* __restrict__ out, int E, int ntiles)
{
    extern __shared__ __align__(1024) char smc[];
    uint32_t smb = s2u(smc);
    int tid = threadIdx.x, wid = tid >> 5, lane = tid & 31;

    float* b1_s = (float*)(smc + OFF_B1);
    float* w2_s = (float*)(smc + OFF_W2);
    float* bk_s = (float*)(smc + OFF_BKs);
    float* bv_s = (float*)(smc + OFF_BVs);
    float* w_sm = (float*)(smc + OFF_WS);

    // stage B image into smem once per CTA
    {
        float4* d0 = (float4*)(smc + OFF_B);
        const float4* s0 = (const float4*)g_B;
        for (int i = tid; i < 4096; i += NT) d0[i] = s0[i];
    }
    if (tid < H) {
        b1_s[tid] = b1[tid]; w2_s[tid] = W2[tid];
        bk_s[tid] = bk[tid]; bv_s[tid] = bv[tid];
    }

    float inv_tc = 1.f / (fabsf(tcp[0]) + 1e-9f);
    float b2v = b2[0];

    // ---- per-warp GEMM tiling: m64 x n32, 2x8 warp grid ----
    int warp_row = wid & 1;
    int warp_col = wid >> 1;
    int n0 = warp_col * 32;
    bool isK = (n0 < 128);

    int ra = lane & 7, ha = (lane >> 3) & 1, kh = lane >> 4;
    uint32_t aXor = (uint32_t)ra << 4;
    uint32_t aKh = (uint32_t)(kh * 16);
    uint32_t aRowLoc = (uint32_t)(warp_row * 64 + ha * 8 + ra) * 256u;

    int qb = lane >> 3, rb = lane & 7;
    uint32_t bXor = (uint32_t)rb << 4;
    uint32_t bKh = (uint32_t)((qb & 1) * 16);
    uint32_t bRow0 = smb + OFF_B + (uint32_t)(n0 + (qb >> 1) * 8 + rb) * 256u;
    uint32_t bRow1 = bRow0 + 16u * 256u;

    int r4 = lane >> 2, c2 = (lane & 3) * 2;

    // gather mapping: 4 threads per edge
    int ge = tid >> 2, gq = tid & 3;
    unsigned xr = (unsigned)(ge & 7) << 4;
    int ldr = lane & ~3;

    __syncthreads();   // b1_s/w2_s ready for prologue gather

    // ---- prologue: full gather of first tile into A0 / dst0 / ss0 ----
    {
        int e0 = blockIdx.x * TILE_E;
        int sn = 0, rr = 0; float tme = 0.f;
        if (gq == 0) {
            int cnt0 = min(TILE_E, E - e0);
            if (ge < cnt0) {
                int ee = e0 + ge;
                int d = dst[ee];
                sn = src[ee]; rr = et[ee];
                float dt = (ts[d] - etime[ee]) * inv_tc;
                tme = 1.f / (1.f + expf(-dt));
                ((int*)(smc + OFF_DST0))[ge] = d;
            } else {
                ((int*)(smc + OFF_DST0))[ge] = 0;
            }
        }
        sn  = __shfl_sync(0xFFFFFFFFu, sn,  ldr);
        rr  = __shfl_sync(0xFFFFFFFFu, rr,  ldr);
        tme = __shfl_sync(0xFFFFFFFFu, tme, ldr);
        const float4* xp  = (const float4*)(x     + (size_t)sn * H) + gq * 8;
        const float4* rp  = (const float4*)(rel   + (size_t)rr * H) + gq * 8;
        const float4* sp  = (const float4*)(g_S1  + (size_t)sn * H) + gq * 8;
        const float4* r2p = (const float4*)(g_R2x + (size_t)rr * H) + gq * 8;
        char* Arow = smc + OFF_A0 + ge * 256;
        float hacc = 0.f;
#pragma unroll
        for (int i = 0; i < 8; i++) {
            float4 stx = __ldg(xp + i), strv = __ldg(rp + i);
            float4 sts1 = __ldg(sp + i), str2 = __ldg(r2p + i);
            GBODY(i, Arow, tme);
        }
        hacc += __shfl_xor_sync(0xFFFFFFFFu, hacc, 1);
        hacc += __shfl_xor_sync(0xFFFFFFFFu, hacc, 2);
        if (gq == 0) {
            float dw = 1.f / (1.f + expf(-(hacc + b2v)));
            ((float*)(smc + OFF_SS0))[ge] = tme * dw;
        }
    }
    __syncthreads();

    int parity = 0;
    for (int t = blockIdx.x; t < ntiles; t += gridDim.x, parity ^= 1) {
        int tn = t + gridDim.x;
        bool haveN = (tn < ntiles);
        int cnt = min(TILE_E, E - t * TILE_E);

        uint32_t aCur = smb + (parity ? OFF_A1 : OFF_A0) + aRowLoc;
        char* Anxt    = smc + (parity ? OFF_A0 : OFF_A1) + ge * 256;
        int*   dstC = (int*)  (smc + (parity ? OFF_DST1 : OFF_DST0));
        int*   dstN = (int*)  (smc + (parity ? OFF_DST0 : OFF_DST1));
        float* ssC  = (float*)(smc + (parity ? OFF_SS1  : OFF_SS0));
        float* ssN  = (float*)(smc + (parity ? OFF_SS0  : OFF_SS1));

        // ---- issue next-tile meta loads (quad leader) ----
        int snN = 0, rrN = 0, dN = 0;
        float etmN = 0.f, tsdN = 0.f;
        bool validN = false;
        if (haveN && gq == 0) {
            int cntN = min(TILE_E, E - tn * TILE_E);
            if (ge < cntN) {
                validN = true;
                int ee = tn * TILE_E + ge;
                dN = dst[ee];
                snN = src[ee]; rrN = et[ee]; etmN = etime[ee];
                tsdN = ts[dN];
            }
        }

        float acc[4][4][4];
#pragma unroll
        for (int mt = 0; mt < 4; mt++)
#pragma unroll
            for (int ng = 0; ng < 4; ng++)
#pragma unroll
                for (int i = 0; i < 4; i++) acc[mt][ng][i] = 0.f;

        // ---- MMA over 8 k-steps, gather of next tile interleaved ----
        float haccN = 0.f, tmeN = 0.f;
        const float4 *xpN = nullptr, *rpN = nullptr, *spN = nullptr, *r2pN = nullptr;
        float4 stx, strv, sts1, str2;

#pragma unroll
        for (int ks = 0; ks < 8; ks++) {
            uint32_t kbB = ((uint32_t)(ks * 32) + bKh) ^ bXor;
            uint32_t bh[8];
            ldsm4(bh + 0, bRow0 + kbB);
            ldsm4(bh + 4, bRow1 + kbB);
            uint32_t kbA = ((uint32_t)(ks * 32) + aKh) ^ aXor;
#pragma unroll
            for (int mt = 0; mt < 4; mt++) {
                uint32_t ah[4];
                ldsm4(ah, aCur + (uint32_t)(mt * 16) * 256u + kbA);
#pragma unroll
                for (int ng = 0; ng < 4; ng++)
                    mma16816(acc[mt][ng], ah, bh + ng * 2);
            }
            if (haveN) {
                if (ks == 0) {
                    if (gq == 0) {
                        if (validN) {
                            float dt = (tsdN - etmN) * inv_tc;
                            tmeN = 1.f / (1.f + expf(-dt));
                        }
                        dstN[ge] = dN;
                    }
                    snN  = __shfl_sync(0xFFFFFFFFu, snN,  ldr);
                    rrN  = __shfl_sync(0xFFFFFFFFu, rrN,  ldr);
                    tmeN = __shfl_sync(0xFFFFFFFFu, tmeN, ldr);
                    xpN  = (const float4*)(x     + (size_t)snN * H) + gq * 8;
                    rpN  = (const float4*)(rel   + (size_t)rrN * H) + gq * 8;
                    spN  = (const float4*)(g_S1  + (size_t)snN * H) + gq * 8;
                    r2pN = (const float4*)(g_R2x + (size_t)rrN * H) + gq * 8;
                    stx = __ldg(xpN); strv = __ldg(rpN); sts1 = __ldg(spN); str2 = __ldg(r2pN);
                } else {
                    {
                        float hacc = haccN;
                        GBODY(ks - 1, Anxt, tmeN);
                        haccN = hacc;
                    }
                    stx = __ldg(xpN + ks); strv = __ldg(rpN + ks);
                    sts1 = __ldg(spN + ks); str2 = __ldg(r2pN + ks);
                }
            }
        }
        if (haveN) {
            {
                float hacc = haccN;
                GBODY(7, Anxt, tmeN);
                haccN = hacc;
            }
            haccN += __shfl_xor_sync(0xFFFFFFFFu, haccN, 1);
            haccN += __shfl_xor_sync(0xFFFFFFFFu, haccN, 2);
            if (gq == 0) {
                float dw = 1.f / (1.f + expf(-(haccN + b2v)));
                ssN[ge] = tmeN * dw;
            }
        }

        // ---- phase 3: K-warps score epilogue (register-resident) ----
        if (isK) {
#pragma unroll
            for (int mt = 0; mt < 4; mt++) {
#pragma unroll
                for (int hf = 0; hf < 2; hf++) {
                    int e = warp_row * 64 + mt * 16 + hf * 8 + r4;
                    int d2 = dstC[e];
                    float sce = ssC[e];
                    const float* qrow = g_Q + (size_t)d2 * H + n0 + c2;
                    float sA = 0.f, sB = 0.f;
#pragma unroll
                    for (int ng = 0; ng < 4; ng++) {
                        float2 bl = *(const float2*)(bk_s + n0 + c2 + ng * 8);
                        float k0 = fmaf(acc[mt][ng][hf * 2 + 0], sce, bl.x);
                        float k1 = fmaf(acc[mt][ng][hf * 2 + 1], sce, bl.y);
                        float2 q2 = __ldg((const float2*)(qrow + ng * 8));
                        float dp = q2.x * k0 + q2.y * k1;
                        if (ng < 2) sA += dp; else sB += dp;
                    }
                    sA += __shfl_xor_sync(0xFFFFFFFFu, sA, 1);
                    sA += __shfl_xor_sync(0xFFFFFFFFu, sA, 2);
                    sB += __shfl_xor_sync(0xFFFFFFFFu, sB, 1);
                    sB += __shfl_xor_sync(0xFFFFFFFFu, sB, 2);
                    if (c2 == 0) {
                        float w0 = expf(sA * 0.25f);
                        float w1 = expf(sB * 0.25f);
                        w_sm[e * 8 + warp_col * 2 + 0] = w0;
                        w_sm[e * 8 + warp_col * 2 + 1] = w1;
                        if (e < cnt) {
                            float* dp2 = &g_denom[(size_t)d2 * NHEAD + warp_col * 2];
                            REDV2(dp2, w0, w1);
                        }
                    }
                }
            }
        }
        __syncthreads();

        // ---- phase 4: V-warps weighted scatter (register-resident) ----
        if (!isK) {
            int vb = n0 - 128;
#pragma unroll
            for (int mt = 0; mt < 4; mt++) {
#pragma unroll
                for (int hf = 0; hf < 2; hf++) {
                    int e = warp_row * 64 + mt * 16 + hf * 8 + r4;
                    if (e < cnt) {
                        int d2 = dstC[e];
                        float sce = ssC[e];
                        float* orow = out + (size_t)d2 * H + vb + c2;
#pragma unroll
                        for (int ng = 0; ng < 4; ng++) {
                            float2 bl = *(const float2*)(bv_s + vb + c2 + ng * 8);
                            float ww = w_sm[e * 8 + ((vb + ng * 8) >> 4)];
                            float v0 = fmaf(acc[mt][ng][hf * 2 + 0], sce, bl.x) * ww;
                            float v1 = fmaf(acc[mt][ng][hf * 2 + 1], sce, bl.y) * ww;
                            REDV2(orow + ng * 8, v0, v1);
                        }
                    }
                }
            }
        }
        __syncthreads();
    }
}

// ---------------- normalize ------------------------------------------------
__global__ void k_norm(float* __restrict__ out, int N)
{
    int idx = blockIdx.x * blockDim.x + threadIdx.x;
    if (idx >= N * H) return;
    int n = idx >> 7, jj = idx & (H - 1);
    float dnm = g_denom[n * NHEAD + (jj >> 4)];
    float v = out[idx];
    out[idx] = (dnm > 0.f) ? v / dnm : 0.f;
}

// ---------------- launch ---------------------------------------------------
extern "C" void kernel_launch(void* const* d_in, const int* in_sizes, int n_in,
                              void* d_out, int out_size)
{
    const float* x     = (const float*)d_in[0];
    const float* ts    = (const float*)d_in[1];
    const int*   src   = (const int*)  d_in[2];
    const int*   dst   = (const int*)  d_in[3];
    const int*   etyp  = (const int*)  d_in[4];
    const float* etime = (const float*)d_in[5];
    const float* rel   = (const float*)d_in[6];
    const float* Wq    = (const float*)d_in[7];
    const float* bq    = (const float*)d_in[8];
    const float* Wk    = (const float*)d_in[9];
    const float* bk    = (const float*)d_in[10];
    const float* Wv    = (const float*)d_in[11];
    const float* bv    = (const float*)d_in[12];
    const float* W1    = (const float*)d_in[13];
    const float* b1    = (const float*)d_in[14];
    const float* W2    = (const float*)d_in[15];
    const float* b2    = (const float*)d_in[16];
    const float* tcp   = (const float*)d_in[17];

    int N    = in_sizes[0] / H;
    int E    = in_sizes[2];
    int NREL = in_sizes[6] / H;
    float* out = (float*)d_out;
    int ntiles = (E + TILE_E - 1) / TILE_E;

    static int smem_set = 0;
    if (!smem_set) {
        cudaFuncSetAttribute(k_edge_mma, cudaFuncAttributeMaxDynamicSharedMemorySize, SMEM_EDGE);
        smem_set = 1;
    }

    k_init <<<2048, 256>>>(out, N, out_size);
    k_rel  <<<NREL, H>>>(rel, W1);
    k_prepw<<<256, H>>>(Wk, Wv);
    k_node <<<(N + TEN - 1) / TEN, H>>>(x, Wq, bq, W1, N);
    k_edge_mma<<<148, NT, SMEM_EDGE>>>(x, ts, src, dst, etyp, etime, rel,
                                       bk, bv, b1, W2, b2, tcp, out, E, ntiles);
    k_norm <<<(N * H + 255) / 256, 256>>>(out, N);
}

// round 11
// speedup vs baseline: 1.2952x; 1.0461x over previous
#include <cuda_runtime.h>
#include <cuda_fp16.h>
#include <cstdint>

#define H       128
#define NHEAD   8
#define N_MAX   50000
#define E_MAX   800000
#define NRELMX  64
#define TEN     32
#define GPAD    36
#define TILE_E  128
#define NT      512

// ---------------- global scratch -------------------------------------------
__device__ float g_Q  [N_MAX * H];
__device__ float g_S1 [N_MAX * H];
__device__ float g_R2x[NRELMX * H];
__device__ float g_denom[N_MAX * NHEAD];
__device__ __half g_B[256 * H];        // [n][k] fp16, 256B rows, XOR-16B swizzle
__device__ int   g_hist[N_MAX];        // zero at module load; re-zeroed by k_norm
__device__ int   g_offs[N_MAX + 1];
__device__ int   g_offsw[N_MAX];
__device__ int   g_perm[E_MAX];

// ---------------- smem layout (edge kernel) --------------------------------
#define OFF_B     0        // 65536
#define OFF_A     65536    // 32768 (fp16 A tile)
#define OFF_KV    65536    // 65536 (aliases A region after GEMM)
#define OFF_BK    131072
#define OFF_BV    131584
#define OFF_B1    132096
#define OFF_W2    132608
#define OFF_DST   133120
#define OFF_SS    133632
#define OFF_WS    134144   // w_sm[128][8] = 4096
#define OFF_SEG   138240   // 128 ints
#define OFF_NSEG  138752
#define SMEM_EDGE 139264

// ---------------- helpers --------------------------------------------------
__device__ __forceinline__ uint32_t s2u(const void* p) {
    uint32_t a;
    asm("{ .reg .u64 t; cvta.to.shared.u64 t, %1; cvt.u32.u64 %0, t; }" : "=r"(a) : "l"(p));
    return a;
}
__device__ __forceinline__ void ldsm4(uint32_t* r, uint32_t addr) {
    asm volatile("ldmatrix.sync.aligned.m8n8.x4.shared.b16 {%0,%1,%2,%3}, [%4];"
                 : "=r"(r[0]), "=r"(r[1]), "=r"(r[2]), "=r"(r[3]) : "r"(addr));
}
__device__ __forceinline__ void mma16816(float* c, const uint32_t* a, const uint32_t* b) {
    asm volatile(
        "mma.sync.aligned.m16n8k16.row.col.f32.f16.f16.f32 "
        "{%0,%1,%2,%3}, {%4,%5,%6,%7}, {%8,%9}, {%0,%1,%2,%3};"
        : "+f"(c[0]), "+f"(c[1]), "+f"(c[2]), "+f"(c[3])
        : "r"(a[0]), "r"(a[1]), "r"(a[2]), "r"(a[3]), "r"(b[0]), "r"(b[1]));
}
#define DUP2(d, s) asm("mov.b64 %0, {%1,%1};" : "=l"(d) : "f"(s))
#define F2MA(acc, a, b) asm("fma.rn.f32x2 %0, %1, %2, %0;" : "+l"(acc) : "l"(a), "l"(b))
#define REDV4(p, a, b, c, d) asm volatile("red.global.add.v4.f32 [%0], {%1,%2,%3,%4};" :: "l"(p), "f"(a), "f"(b), "f"(c), "f"(d) : "memory")

// ---------------- pre1: zero out+denom, histogram dst ----------------------
__global__ void k_pre1(const int* __restrict__ dst, float* __restrict__ out,
                       int N, int E, int outElems) {
    int i = blockIdx.x * blockDim.x + threadIdx.x;
    int stride = gridDim.x * blockDim.x;
    for (int idx = i; idx < outElems; idx += stride) out[idx] = 0.f;
    for (int idx = i; idx < N * NHEAD; idx += stride) g_denom[idx] = 0.f;
    for (int idx = i; idx < E; idx += stride) atomicAdd(&g_hist[dst[idx]], 1);
}

// ---------------- scan: exclusive prefix over hist (1 CTA) -----------------
__global__ void __launch_bounds__(1024) k_scan(int N, int E) {
    __shared__ int sm[1024];
    int t = threadIdx.x;
    int chunk = (N + 1023) >> 10;
    int base = t * chunk;
    int s = 0;
    for (int i = 0; i < chunk; i++) {
        int ix = base + i;
        if (ix < N) s += g_hist[ix];
    }
    sm[t] = s;
    __syncthreads();
    for (int off = 1; off < 1024; off <<= 1) {
        int v = (t >= off) ? sm[t - off] : 0;
        __syncthreads();
        sm[t] += v;
        __syncthreads();
    }
    int run = sm[t] - s;  // exclusive prefix of this chunk
    for (int i = 0; i < chunk; i++) {
        int ix = base + i;
        if (ix < N) {
            g_offs[ix] = run;
            g_offsw[ix] = run;
            run += g_hist[ix];
        }
    }
    if (t == 0) g_offs[N] = E;
}

// ---------------- pre3: scatter-perm + weight image + R2x + node precompute
__global__ void k_pre3(
    const int* __restrict__ dst, const int* __restrict__ srcI,
    const float* __restrict__ x, const float* __restrict__ Wq,
    const float* __restrict__ bq, const float* __restrict__ W1,
    const float* __restrict__ rel,
    const float* __restrict__ Wk, const float* __restrict__ Wv,
    int N, int E, int NREL, int NB_SC, int NB_PW, int NB_RL)
{
    int b = blockIdx.x, tid = threadIdx.x;
    if (b < NB_SC) {
        // scatter permutation
        int e = b * 256 + tid;
        if (e < E) {
            int d = dst[e];
            int pos = atomicAdd(&g_offsw[d], 1);
            g_perm[pos] = e;
        }
        return;
    }
    b -= NB_SC;
    if (b < NB_PW) {
        // weight image BT[n][k] fp16, swizzled
        int n = b * 2 + (tid >> 7);
        int k = tid & 127;
        float w = (n < H) ? Wk[k * H + n] : Wv[k * H + (n - H)];
        unsigned kb = (unsigned)k * 2u;
        unsigned phys = (unsigned)n * 256u + (kb ^ ((unsigned)(n & 7) << 4));
        *(__half*)((char*)g_B + phys) = __float2half_rn(w);
        return;
    }
    b -= NB_PW;
    if (b < NB_RL) {
        int r = b * 2 + (tid >> 7);
        int j = tid & 127;
        if (r < NREL) {
            float acc = W1[256 * H + j];
            for (int i = 0; i < H; i++)
                acc += rel[r * H + i] * W1[(H + i) * H + j];
            g_R2x[r * H + j] = acc;
        }
        return;
    }
    b -= NB_RL;
    // node precompute: 2 groups of 128 threads, TEN nodes each
    {
        __shared__ __align__(16) float xt2[2][H * GPAD];
        int g = tid >> 7, j = tid & 127;
        float* xt = xt2[g];
        int n0 = (b * 2 + g) * TEN;
        int cnt = min(TEN, N - n0);
        for (int e = 0; e < TEN; e++)
            xt[j * GPAD + e] = (e < cnt) ? x[(size_t)(n0 + e) * H + j] : 0.f;
        __syncthreads();

        unsigned long long aq[TEN / 2], as_[TEN / 2];
#pragma unroll
        for (int i = 0; i < TEN / 2; i++) { aq[i] = 0ull; as_[i] = 0ull; }
        for (int kk = 0; kk < H; kk++) {
            float wq = Wq[kk * H + j];
            float w1 = W1[kk * H + j];
            unsigned long long wq2, w12;
            DUP2(wq2, wq);
            DUP2(w12, w1);
            const ulonglong2* gp = (const ulonglong2*)(&xt[kk * GPAD]);
#pragma unroll
            for (int q4 = 0; q4 < TEN / 4; q4++) {
                ulonglong2 gg = gp[q4];
                F2MA(aq[q4 * 2],      gg.x, wq2);
                F2MA(aq[q4 * 2 + 1],  gg.y, wq2);
                F2MA(as_[q4 * 2],     gg.x, w12);
                F2MA(as_[q4 * 2 + 1], gg.y, w12);
            }
        }
        float bqj = bq[j];
        for (int e = 0; e < cnt; e++) {
            float vq = (e & 1) ? __uint_as_float((unsigned)(aq[e >> 1] >> 32))
                               : __uint_as_float((unsigned)(aq[e >> 1] & 0xFFFFFFFFull));
            float vs = (e & 1) ? __uint_as_float((unsigned)(as_[e >> 1] >> 32))
                               : __uint_as_float((unsigned)(as_[e >> 1] & 0xFFFFFFFFull));
            g_Q [(n0 + e) * H + j] = vq + bqj;
            g_S1[(n0 + e) * H + j] = vs;
        }
    }
}

// ---------------- persistent fused edge kernel (sorted, segmented epilogue)
__global__ void __launch_bounds__(NT, 1) k_edge_mma(
    const float* __restrict__ x, const float* __restrict__ ts,
    const int* __restrict__ src, const int* __restrict__ dst, const int* __restrict__ et,
    const float* __restrict__ etime, const float* __restrict__ rel,
    const float* __restrict__ bk, const float* __restrict__ bv,
    const float* __restrict__ b1, const float* __restrict__ W2,
    const float* __restrict__ b2, const float* __restrict__ tcp,
    float* __restrict__ out, int E, int ntiles)
{
    extern __shared__ __align__(1024) char smc[];
    uint32_t smb = s2u(smc);
    int tid = threadIdx.x, wid = tid >> 5, lane = tid & 31;

    float* bk_s  = (float*)(smc + OFF_BK);
    float* bv_s  = (float*)(smc + OFF_BV);
    float* b1_s  = (float*)(smc + OFF_B1);
    float* w2_s  = (float*)(smc + OFF_W2);
    int*   dst_s = (int*)  (smc + OFF_DST);
    float* ss_s  = (float*)(smc + OFF_SS);
    float* w_sm  = (float*)(smc + OFF_WS);
    int*   seg_s = (int*)  (smc + OFF_SEG);
    int*   nseg_p= (int*)  (smc + OFF_NSEG);

    // stage B image into smem once per CTA
    {
        float4* d0 = (float4*)(smc + OFF_B);
        const float4* s0 = (const float4*)g_B;
        for (int i = tid; i < 4096; i += NT) d0[i] = s0[i];
    }
    if (tid < H) { bk_s[tid] = bk[tid]; bv_s[tid] = bv[tid]; b1_s[tid] = b1[tid]; w2_s[tid] = W2[tid]; }
    __syncthreads();

    float inv_tc = 1.f / (fabsf(tcp[0]) + 1e-9f);
    float b2v = b2[0];

    // ---- per-warp GEMM tiling: m64 x n32, 2x8 warp grid ----
    int warp_row = wid & 1;
    int warp_col = wid >> 1;
    int n0 = warp_col * 32;
    bool isK = (n0 < 128);

    int ra = lane & 7, ha = (lane >> 3) & 1, kh = lane >> 4;
    uint32_t aXor = (uint32_t)ra << 4;
    uint32_t aKh = (uint32_t)(kh * 16);
    uint32_t aRowBase = smb + OFF_A + (uint32_t)(warp_row * 64 + ha * 8 + ra) * 256u;

    int qb = lane >> 3, rb = lane & 7;
    uint32_t bXor = (uint32_t)rb << 4;
    uint32_t bKh = (uint32_t)((qb & 1) * 16);
    uint32_t bRow0 = smb + OFF_B + (uint32_t)(n0 + (qb >> 1) * 8 + rb) * 256u;
    uint32_t bRow1 = bRow0 + 16u * 256u;

    int r4 = lane >> 2, c2 = (lane & 3) * 2;
    int ge = tid >> 2, gq = tid & 3;
    int ldr = lane & ~3;

    for (int t = blockIdx.x; t < ntiles; t += gridDim.x) {
        int e0 = t * TILE_E;
        int cnt = min(TILE_E, E - e0);

        // ---- phase 1: meta via perm (quad leader) + gather + dw ----
        {
            int sn = 0, rr = 0;
            float tme = 0.f;
            if (gq == 0) {
                if (ge < cnt) {
                    int ee = __ldg(&g_perm[e0 + ge]);
                    int d = dst[ee];
                    sn = src[ee]; rr = et[ee];
                    float dt = (ts[d] - etime[ee]) * inv_tc;
                    tme = 1.f / (1.f + expf(-dt));
                    dst_s[ge] = d;
                } else {
                    dst_s[ge] = 0;
                }
            }
            sn  = __shfl_sync(0xFFFFFFFFu, sn,  ldr);
            rr  = __shfl_sync(0xFFFFFFFFu, rr,  ldr);
            tme = __shfl_sync(0xFFFFFFFFu, tme, ldr);

            const float4* xp  = (const float4*)(x     + (size_t)sn * H) + gq * 8;
            const float4* rp  = (const float4*)(rel   + (size_t)rr * H) + gq * 8;
            const float4* sp  = (const float4*)(g_S1  + (size_t)sn * H) + gq * 8;
            const float4* r2p = (const float4*)(g_R2x + (size_t)rr * H) + gq * 8;
            char* Ah = smc + OFF_A + ge * 256;
            unsigned xr = (unsigned)(ge & 7) << 4;
            float hacc = 0.f;
#pragma unroll
            for (int i = 0; i < 8; i++) {
                float4 xv = __ldg(xp + i), rv = __ldg(rp + i);
                float4 s1 = __ldg(sp + i), r2 = __ldg(r2p + i);
                int col = gq * 32 + i * 4;
                float4 b14 = *(const float4*)(b1_s + col);
                float4 w24 = *(const float4*)(w2_s + col);
                float g0 = xv.x * rv.x, g1 = xv.y * rv.y, g2 = xv.z * rv.z, g3 = xv.w * rv.w;
                hacc += fmaxf(fmaf(tme, r2.x, s1.x + b14.x), 0.f) * w24.x;
                hacc += fmaxf(fmaf(tme, r2.y, s1.y + b14.y), 0.f) * w24.y;
                hacc += fmaxf(fmaf(tme, r2.z, s1.z + b14.z), 0.f) * w24.z;
                hacc += fmaxf(fmaf(tme, r2.w, s1.w + b14.w), 0.f) * w24.w;
                __half2 h01 = __floats2half2_rn(g0, g1);
                __half2 h23 = __floats2half2_rn(g2, g3);
                unsigned kb = (unsigned)(gq * 64 + i * 8);
                uint2 uh; uh.x = *(unsigned*)&h01; uh.y = *(unsigned*)&h23;
                *(uint2*)(Ah + (kb ^ xr)) = uh;
            }
            hacc += __shfl_xor_sync(0xFFFFFFFFu, hacc, 1);
            hacc += __shfl_xor_sync(0xFFFFFFFFu, hacc, 2);
            if (gq == 0) {
                float dw = 1.f / (1.f + expf(-(hacc + b2v)));
                ss_s[ge] = tme * dw;
            }
        }
        if (tid == 0) nseg_p[0] = 0;
        __syncthreads();

        // ---- phase 2: GEMM 128x256x128 fp16, m64n32 per warp ----
        float acc[4][4][4];
#pragma unroll
        for (int mt = 0; mt < 4; mt++)
#pragma unroll
            for (int ng = 0; ng < 4; ng++)
#pragma unroll
                for (int i = 0; i < 4; i++) acc[mt][ng][i] = 0.f;

        for (int ks = 0; ks < 8; ks++) {
            uint32_t kbB = ((uint32_t)(ks * 32) + bKh) ^ bXor;
            uint32_t bh[8];
            ldsm4(bh + 0, bRow0 + kbB);
            ldsm4(bh + 4, bRow1 + kbB);
            uint32_t kbA = ((uint32_t)(ks * 32) + aKh) ^ aXor;
#pragma unroll
            for (int mt = 0; mt < 4; mt++) {
                uint32_t ah[4];
                ldsm4(ah, aRowBase + (uint32_t)(mt * 16) * 256u + kbA);
#pragma unroll
                for (int ng = 0; ng < 4; ng++)
                    mma16816(acc[mt][ng], ah, bh + ng * 2);
            }
        }
        __syncthreads();   // A free; KV aliases it

        // ---- phase 3: K-warps stage K; V-warps build segment list ----
        if (isK) {
#pragma unroll
            for (int mt = 0; mt < 4; mt++) {
#pragma unroll
                for (int ng = 0; ng < 4; ng++) {
                    int ee = warp_row * 64 + mt * 16 + r4;
                    unsigned jb = (unsigned)((n0 + ng * 8 + c2) * 4);
                    char* base = smc + OFF_KV;
                    *(float2*)(base + ee * 512 + (jb ^ ((unsigned)(ee & 31) << 4))) =
                        make_float2(acc[mt][ng][0], acc[mt][ng][1]);
                    int ee2 = ee + 8;
                    *(float2*)(base + ee2 * 512 + (jb ^ ((unsigned)(ee2 & 31) << 4))) =
                        make_float2(acc[mt][ng][2], acc[mt][ng][3]);
                }
            }
        } else {
            int e = tid - 256;
            if (e >= 0 && e < 128) {
                bool bnd = (e < cnt) && (e == 0 || dst_s[e] != dst_s[e - 1]);
                if (bnd) {
                    int s = atomicAdd(nseg_p, 1);
                    seg_s[s] = e;
                }
            }
        }
        __syncthreads();

        // ---- phase 4: scores -> w_sm (no atomics) ----
        {
            int qq = wid & 3;
            int e = (wid >> 2) * 32 + lane;
            int d2 = dst_s[e];
            float sce = ss_s[e];
            const float* qrow = g_Q + (size_t)d2 * H;
            char* kbase = smc + OFF_KV + e * 512;
            unsigned xr = (unsigned)(e & 31) << 4;
            float s0 = 0.f, s1 = 0.f;
#pragma unroll
            for (int i = 0; i < 8; i++) {
                unsigned jb = (unsigned)(qq * 128 + i * 16);
                float4 kr = *(float4*)(kbase + (jb ^ xr));
                int j = qq * 32 + i * 4;
                float4 q4 = __ldg((const float4*)(qrow + j));
                float k0 = fmaf(kr.x, sce, bk_s[j + 0]);
                float k1 = fmaf(kr.y, sce, bk_s[j + 1]);
                float k2 = fmaf(kr.z, sce, bk_s[j + 2]);
                float k3 = fmaf(kr.w, sce, bk_s[j + 3]);
                float dp = q4.x * k0 + q4.y * k1 + q4.z * k2 + q4.w * k3;
                if (i < 4) s0 += dp; else s1 += dp;
            }
            w_sm[e * 8 + 2 * qq + 0] = expf(s0 * 0.25f);
            w_sm[e * 8 + 2 * qq + 1] = expf(s1 * 0.25f);
        }
        __syncthreads();

        int ns = nseg_p[0];

        // ---- phase 5: V-warps stage V; K-warps segmented denom ----
        if (!isK) {
#pragma unroll
            for (int mt = 0; mt < 4; mt++) {
#pragma unroll
                for (int ng = 0; ng < 4; ng++) {
                    int ee = warp_row * 64 + mt * 16 + r4;
                    unsigned jb = (unsigned)((n0 - 128 + ng * 8 + c2) * 4);
                    char* base = smc + OFF_KV;
                    *(float2*)(base + ee * 512 + (jb ^ ((unsigned)(ee & 31) << 4))) =
                        make_float2(acc[mt][ng][0], acc[mt][ng][1]);
                    int ee2 = ee + 8;
                    *(float2*)(base + ee2 * 512 + (jb ^ ((unsigned)(ee2 & 31) << 4))) =
                        make_float2(acc[mt][ng][2], acc[mt][ng][3]);
                }
            }
        } else {
            for (int idx = tid; idx < ns * NHEAD; idx += 256) {
                int s = idx >> 3, h = idx & 7;
                int st = seg_s[s];
                int d = dst_s[st];
                int gs = __ldg(&g_offs[d]), gend = __ldg(&g_offs[d + 1]);
                int lend = min(cnt, gend - e0);
                float sum = 0.f;
                for (int e = st; e < lend; e++) sum += w_sm[e * 8 + h];
                bool interior = (gs >= e0) && (gend <= e0 + cnt);
                if (interior) g_denom[(size_t)d * NHEAD + h] = sum;
                else atomicAdd(&g_denom[(size_t)d * NHEAD + h], sum);
            }
        }
        __syncthreads();

        // ---- phase 6: segmented V reduce, warp per segment ----
        {
            float4 bv4 = *(const float4*)(bv_s + lane * 4);
            int hh = lane >> 2;
            for (int s = wid; s < ns; s += 16) {
                int st = seg_s[s];
                int d = dst_s[st];
                int gs = __ldg(&g_offs[d]), gend = __ldg(&g_offs[d + 1]);
                int lend = min(cnt, gend - e0);
                bool interior = (gs >= e0) && (gend <= e0 + cnt);
                float4 a4 = make_float4(0.f, 0.f, 0.f, 0.f);
                for (int e = st; e < lend; e++) {
                    float sce = ss_s[e];
                    float ww = w_sm[e * 8 + hh];
                    char* vrow = smc + OFF_KV + e * 512;
                    float4 vr = *(float4*)(vrow + (((unsigned)(lane * 16)) ^ ((unsigned)(e & 31) << 4)));
                    a4.x += fmaf(vr.x, sce, bv4.x) * ww;
                    a4.y += fmaf(vr.y, sce, bv4.y) * ww;
                    a4.z += fmaf(vr.z, sce, bv4.z) * ww;
                    a4.w += fmaf(vr.w, sce, bv4.w) * ww;
                }
                float* orow = out + (size_t)d * H + lane * 4;
                if (interior) *(float4*)orow = a4;
                else REDV4(orow, a4.x, a4.y, a4.z, a4.w);
            }
        }
        __syncthreads();
    }
}

// ---------------- normalize + re-zero hist ---------------------------------
__global__ void k_norm(float* __restrict__ out, int N)
{
    int idx = blockIdx.x * blockDim.x + threadIdx.x;
    if (idx < N) g_hist[idx] = 0;
    if (idx >= N * H) return;
    int n = idx >> 7, jj = idx & (H - 1);
    float dnm = g_denom[n * NHEAD + (jj >> 4)];
    float v = out[idx];
    out[idx] = (dnm > 0.f) ? v / dnm : 0.f;
}

// ---------------- launch ---------------------------------------------------
extern "C" void kernel_launch(void* const* d_in, const int* in_sizes, int n_in,
                              void* d_out, int out_size)
{
    const float* x     = (const float*)d_in[0];
    const float* ts    = (const float*)d_in[1];
    const int*   src   = (const int*)  d_in[2];
    const int*   dst   = (const int*)  d_in[3];
    const int*   etyp  = (const int*)  d_in[4];
    const float* etime = (const float*)d_in[5];
    const float* rel   = (const float*)d_in[6];
    const float* Wq    = (const float*)d_in[7];
    const float* bq    = (const float*)d_in[8];
    const float* Wk    = (const float*)d_in[9];
    const float* bk    = (const float*)d_in[10];
    const float* Wv    = (const float*)d_in[11];
    const float* bv    = (const float*)d_in[12];
    const float* W1    = (const float*)d_in[13];
    const float* b1    = (const float*)d_in[14];
    const float* W2    = (const float*)d_in[15];
    const float* b2    = (const float*)d_in[16];
    const float* tcp   = (const float*)d_in[17];

    int N    = in_sizes[0] / H;
    int E    = in_sizes[2];
    int NREL = in_sizes[6] / H;
    float* out = (float*)d_out;
    int ntiles = (E + TILE_E - 1) / TILE_E;

    int NB_SC = (E + 255) / 256;
    int NB_PW = 128;
    int NB_RL = (NREL + 1) / 2;
    int NB_ND = ((N + TEN - 1) / TEN + 1) / 2;
    int NB = NB_SC + NB_PW + NB_RL + NB_ND;

    static int smem_set = 0;
    if (!smem_set) {
        cudaFuncSetAttribute(k_edge_mma, cudaFuncAttributeMaxDynamicSharedMemorySize, SMEM_EDGE);
        smem_set = 1;
    }

    k_pre1<<<2048, 256>>>(dst, out, N, E, out_size);
    k_scan<<<1, 1024>>>(N, E);
    k_pre3<<<NB, 256>>>(dst, src, x, Wq, bq, W1, rel, Wk, Wv,
                        N, E, NREL, NB_SC, NB_PW, NB_RL);
    k_edge_mma<<<148, NT, SMEM_EDGE>>>(x, ts, src, dst, etyp, etime, rel,
                                       bk, bv, b1, W2, b2, tcp, out, E, ntiles);
    k_norm<<<(N * H + 255) / 256, 256>>>(out, N);
}

// round 13
// speedup vs baseline: 2.0016x; 1.5454x over previous
#include <cuda_runtime.h>
#include <cuda_fp16.h>
#include <cstdint>

#define H       128
#define NHEAD   8
#define N_MAX   50000
#define E_MAX   800000
#define NRELMX  64
#define TEN     32
#define GPAD    36
#define TILE_E  128
#define NT      512

// ---------------- global scratch -------------------------------------------
__device__ float g_Q  [N_MAX * H];
__device__ float g_S1 [N_MAX * H];
__device__ float g_R2x[NRELMX * H];
__device__ float g_denom[N_MAX * NHEAD];
__device__ __half g_B[256 * H];        // [n][k] fp16, 256B rows, XOR-16B swizzle
__device__ int   g_hist[N_MAX];        // zero at module load; re-zeroed by k_norm
__device__ int   g_offs[N_MAX + 1];
__device__ int   g_offsw[N_MAX];
__device__ int   g_perm[E_MAX];

// ---------------- smem layout (edge kernel) --------------------------------
#define OFF_B     0        // 65536
#define OFF_A     65536    // 32768 (fp16 A tile)
#define OFF_KV    65536    // 65536 (aliases A region after GEMM)
#define OFF_BK    131072
#define OFF_BV    131584
#define OFF_B1    132096
#define OFF_W2    132608
#define OFF_DST   133120
#define OFF_SS    133632
#define OFF_WS    134144   // w_sm[128][8] = 4096
#define OFF_SEG   138240   // 128 ints
#define OFF_NSEG  138752
#define SMEM_EDGE 139264

// ---------------- helpers --------------------------------------------------
__device__ __forceinline__ uint32_t s2u(const void* p) {
    uint32_t a;
    asm("{ .reg .u64 t; cvta.to.shared.u64 t, %1; cvt.u32.u64 %0, t; }" : "=r"(a) : "l"(p));
    return a;
}
__device__ __forceinline__ void ldsm4(uint32_t* r, uint32_t addr) {
    asm volatile("ldmatrix.sync.aligned.m8n8.x4.shared.b16 {%0,%1,%2,%3}, [%4];"
                 : "=r"(r[0]), "=r"(r[1]), "=r"(r[2]), "=r"(r[3]) : "r"(addr));
}
__device__ __forceinline__ void mma16816(float* c, const uint32_t* a, const uint32_t* b) {
    asm volatile(
        "mma.sync.aligned.m16n8k16.row.col.f32.f16.f16.f32 "
        "{%0,%1,%2,%3}, {%4,%5,%6,%7}, {%8,%9}, {%0,%1,%2,%3};"
        : "+f"(c[0]), "+f"(c[1]), "+f"(c[2]), "+f"(c[3])
        : "r"(a[0]), "r"(a[1]), "r"(a[2]), "r"(a[3]), "r"(b[0]), "r"(b[1]));
}
#define DUP2(d, s) asm("mov.b64 %0, {%1,%1};" : "=l"(d) : "f"(s))
#define F2MA(acc, a, b) asm("fma.rn.f32x2 %0, %1, %2, %0;" : "+l"(acc) : "l"(a), "l"(b))
#define REDV4(p, a, b, c, d) asm volatile("red.global.add.v4.f32 [%0], {%1,%2,%3,%4};" :: "l"(p), "f"(a), "f"(b), "f"(c), "f"(d) : "memory")

// ---------------- pre1: zero out+denom, histogram dst ----------------------
__global__ void k_pre1(const int* __restrict__ dst, float* __restrict__ out,
                       int N, int E, int outElems) {
    int i = blockIdx.x * blockDim.x + threadIdx.x;
    int stride = gridDim.x * blockDim.x;
    for (int idx = i; idx < outElems; idx += stride) out[idx] = 0.f;
    for (int idx = i; idx < N * NHEAD; idx += stride) g_denom[idx] = 0.f;
    for (int idx = i; idx < E; idx += stride) atomicAdd(&g_hist[dst[idx]], 1);
}

// ---------------- scan: exclusive prefix over hist (1 CTA) -----------------
__global__ void __launch_bounds__(1024) k_scan(int N, int E) {
    __shared__ int sm[1024];
    int t = threadIdx.x;
    int chunk = (N + 1023) >> 10;
    int base = t * chunk;
    int s = 0;
    for (int i = 0; i < chunk; i++) {
        int ix = base + i;
        if (ix < N) s += g_hist[ix];
    }
    sm[t] = s;
    __syncthreads();
    for (int off = 1; off < 1024; off <<= 1) {
        int v = (t >= off) ? sm[t - off] : 0;
        __syncthreads();
        sm[t] += v;
        __syncthreads();
    }
    int run = sm[t] - s;
    for (int i = 0; i < chunk; i++) {
        int ix = base + i;
        if (ix < N) {
            g_offs[ix] = run;
            g_offsw[ix] = run;
            run += g_hist[ix];
        }
    }
    if (t == 0) g_offs[N] = E;
}

// ---------------- pre3: scatter-perm + weight image + R2x + node precompute
__global__ void k_pre3(
    const int* __restrict__ dst, const int* __restrict__ srcI,
    const float* __restrict__ x, const float* __restrict__ Wq,
    const float* __restrict__ bq, const float* __restrict__ W1,
    const float* __restrict__ rel,
    const float* __restrict__ Wk, const float* __restrict__ Wv,
    int N, int E, int NREL, int NB_SC, int NB_PW, int NB_RL)
{
    int b = blockIdx.x, tid = threadIdx.x;
    if (b < NB_SC) {
        int e = b * 256 + tid;
        if (e < E) {
            int d = dst[e];
            int pos = atomicAdd(&g_offsw[d], 1);
            g_perm[pos] = e;
        }
        return;
    }
    b -= NB_SC;
    if (b < NB_PW) {
        int n = b * 2 + (tid >> 7);
        int k = tid & 127;
        float w = (n < H) ? Wk[k * H + n] : Wv[k * H + (n - H)];
        unsigned kb = (unsigned)k * 2u;
        unsigned phys = (unsigned)n * 256u + (kb ^ ((unsigned)(n & 7) << 4));
        *(__half*)((char*)g_B + phys) = __float2half_rn(w);
        return;
    }
    b -= NB_PW;
    if (b < NB_RL) {
        int r = b * 2 + (tid >> 7);
        int j = tid & 127;
        if (r < NREL) {
            float acc = W1[256 * H + j];
            for (int i = 0; i < H; i++)
                acc += rel[r * H + i] * W1[(H + i) * H + j];
            g_R2x[r * H + j] = acc;
        }
        return;
    }
    b -= NB_RL;
    {
        __shared__ __align__(16) float xt2[2][H * GPAD];
        int g = tid >> 7, j = tid & 127;
        float* xt = xt2[g];
        int n0 = (b * 2 + g) * TEN;
        int cnt = min(TEN, N - n0);
        for (int e = 0; e < TEN; e++)
            xt[j * GPAD + e] = (e < cnt) ? x[(size_t)(n0 + e) * H + j] : 0.f;
        __syncthreads();

        unsigned long long aq[TEN / 2], as_[TEN / 2];
#pragma unroll
        for (int i = 0; i < TEN / 2; i++) { aq[i] = 0ull; as_[i] = 0ull; }
        for (int kk = 0; kk < H; kk++) {
            float wq = Wq[kk * H + j];
            float w1 = W1[kk * H + j];
            unsigned long long wq2, w12;
            DUP2(wq2, wq);
            DUP2(w12, w1);
            const ulonglong2* gp = (const ulonglong2*)(&xt[kk * GPAD]);
#pragma unroll
            for (int q4 = 0; q4 < TEN / 4; q4++) {
                ulonglong2 gg = gp[q4];
                F2MA(aq[q4 * 2],      gg.x, wq2);
                F2MA(aq[q4 * 2 + 1],  gg.y, wq2);
                F2MA(as_[q4 * 2],     gg.x, w12);
                F2MA(as_[q4 * 2 + 1], gg.y, w12);
            }
        }
        float bqj = bq[j];
        for (int e = 0; e < cnt; e++) {
            float vq = (e & 1) ? __uint_as_float((unsigned)(aq[e >> 1] >> 32))
                               : __uint_as_float((unsigned)(aq[e >> 1] & 0xFFFFFFFFull));
            float vs = (e & 1) ? __uint_as_float((unsigned)(as_[e >> 1] >> 32))
                               : __uint_as_float((unsigned)(as_[e >> 1] & 0xFFFFFFFFull));
            g_Q [(n0 + e) * H + j] = vq + bqj;
            g_S1[(n0 + e) * H + j] = vs;
        }
    }
}

// ---------------- persistent fused edge kernel (coalesced row gather) ------
__global__ void __launch_bounds__(NT, 1) k_edge_mma(
    const float* __restrict__ x, const float* __restrict__ ts,
    const int* __restrict__ src, const int* __restrict__ dst, const int* __restrict__ et,
    const float* __restrict__ etime, const float* __restrict__ rel,
    const float* __restrict__ bk, const float* __restrict__ bv,
    const float* __restrict__ b1, const float* __restrict__ W2,
    const float* __restrict__ b2, const float* __restrict__ tcp,
    float* __restrict__ out, int E, int ntiles)
{
    extern __shared__ __align__(1024) char smc[];
    uint32_t smb = s2u(smc);
    int tid = threadIdx.x, wid = tid >> 5, lane = tid & 31;

    float* bk_s  = (float*)(smc + OFF_BK);
    float* bv_s  = (float*)(smc + OFF_BV);
    float* b1_s  = (float*)(smc + OFF_B1);
    float* w2_s  = (float*)(smc + OFF_W2);
    int*   dst_s = (int*)  (smc + OFF_DST);
    float* ss_s  = (float*)(smc + OFF_SS);
    float* w_sm  = (float*)(smc + OFF_WS);
    int*   seg_s = (int*)  (smc + OFF_SEG);
    int*   nseg_p= (int*)  (smc + OFF_NSEG);

    // stage B image into smem once per CTA
    {
        float4* d0 = (float4*)(smc + OFF_B);
        const float4* s0 = (const float4*)g_B;
        for (int i = tid; i < 4096; i += NT) d0[i] = s0[i];
    }
    if (tid < H) { bk_s[tid] = bk[tid]; bv_s[tid] = bv[tid]; b1_s[tid] = b1[tid]; w2_s[tid] = W2[tid]; }
    __syncthreads();

    float inv_tc = 1.f / (fabsf(tcp[0]) + 1e-9f);
    float b2v = b2[0];

    // ---- per-warp GEMM tiling: m64 x n32, 2x8 warp grid ----
    int warp_row = wid & 1;
    int warp_col = wid >> 1;
    int n0 = warp_col * 32;
    bool isK = (n0 < 128);

    int ra = lane & 7, ha = (lane >> 3) & 1, kh = lane >> 4;
    uint32_t aXor = (uint32_t)ra << 4;
    uint32_t aKh = (uint32_t)(kh * 16);
    uint32_t aRowBase = smb + OFF_A + (uint32_t)(warp_row * 64 + ha * 8 + ra) * 256u;

    int qb = lane >> 3, rb = lane & 7;
    uint32_t bXor = (uint32_t)rb << 4;
    uint32_t bKh = (uint32_t)((qb & 1) * 16);
    uint32_t bRow0 = smb + OFF_B + (uint32_t)(n0 + (qb >> 1) * 8 + rb) * 256u;
    uint32_t bRow1 = bRow0 + 16u * 256u;

    int r4 = lane >> 2, c2 = (lane & 3) * 2;
    int ew0 = wid * 8;   // warp's 8 edges (gather/score phases)

    // hoisted per-lane col constants
    float4 b14 = *(const float4*)(b1_s + lane * 4);
    float4 w24 = *(const float4*)(w2_s + lane * 4);
    float4 bk4 = *(const float4*)(bk_s + lane * 4);
    float4 bv4 = *(const float4*)(bv_s + lane * 4);
    int head = lane >> 2;

    for (int t = blockIdx.x; t < ntiles; t += gridDim.x) {
        int e0 = t * TILE_E;
        int cnt = min(TILE_E, E - e0);

        // ---- phase 1: meta (lanes<8) + coalesced row gather + gating ----
        {
            int sn = 0, rr = 0, dd = 0;
            float tme = 0.f;
            if (lane < 8) {
                int ge = ew0 + lane;
                if (ge < cnt) {
                    int ee = __ldg(&g_perm[e0 + ge]);
                    dd = dst[ee];
                    sn = src[ee]; rr = et[ee];
                    float dt = (ts[dd] - etime[ee]) * inv_tc;
                    tme = 1.f / (1.f + expf(-dt));
                }
                dst_s[ge] = dd;
            }
            float hsum = 0.f;
#pragma unroll
            for (int e = 0; e < 8; e++) {
                int ge = ew0 + e;
                int sne = __shfl_sync(0xFFFFFFFFu, sn, e);
                int rre = __shfl_sync(0xFFFFFFFFu, rr, e);
                float tmee = __shfl_sync(0xFFFFFFFFu, tme, e);
                float4 xv = __ldg((const float4*)(x     + (size_t)sne * H) + lane);
                float4 rv = __ldg((const float4*)(rel   + (size_t)rre * H) + lane);
                float4 s1 = __ldg((const float4*)(g_S1  + (size_t)sne * H) + lane);
                float4 r2 = __ldg((const float4*)(g_R2x + (size_t)rre * H) + lane);
                float g0 = xv.x * rv.x, g1 = xv.y * rv.y, g2 = xv.z * rv.z, g3 = xv.w * rv.w;
                float p;
                p  = fmaxf(fmaf(tmee, r2.x, s1.x + b14.x), 0.f) * w24.x;
                p += fmaxf(fmaf(tmee, r2.y, s1.y + b14.y), 0.f) * w24.y;
                p += fmaxf(fmaf(tmee, r2.z, s1.z + b14.z), 0.f) * w24.z;
                p += fmaxf(fmaf(tmee, r2.w, s1.w + b14.w), 0.f) * w24.w;
                __half2 h01 = __floats2half2_rn(g0, g1);
                __half2 h23 = __floats2half2_rn(g2, g3);
                char* Ah = smc + OFF_A + ge * 256;
                unsigned kb = (unsigned)(lane * 8);
                unsigned xr = (unsigned)(ge & 7) << 4;
                uint2 uh; uh.x = *(unsigned*)&h01; uh.y = *(unsigned*)&h23;
                *(uint2*)(Ah + (kb ^ xr)) = uh;
                // warp reduce this edge's gating dot
                p += __shfl_xor_sync(0xFFFFFFFFu, p, 16);
                p += __shfl_xor_sync(0xFFFFFFFFu, p, 8);
                p += __shfl_xor_sync(0xFFFFFFFFu, p, 4);
                p += __shfl_xor_sync(0xFFFFFFFFu, p, 2);
                p += __shfl_xor_sync(0xFFFFFFFFu, p, 1);
                if (lane == e) hsum = p;
            }
            if (lane < 8) {
                float dw = 1.f / (1.f + expf(-(hsum + b2v)));
                ss_s[ew0 + lane] = tme * dw;
            }
        }
        if (tid == 0) nseg_p[0] = 0;
        __syncthreads();

        // ---- phase 2: GEMM 128x256x128 fp16, m64n32 per warp ----
        float acc[4][4][4];
#pragma unroll
        for (int mt = 0; mt < 4; mt++)
#pragma unroll
            for (int ng = 0; ng < 4; ng++)
#pragma unroll
                for (int i = 0; i < 4; i++) acc[mt][ng][i] = 0.f;

        for (int ks = 0; ks < 8; ks++) {
            uint32_t kbB = ((uint32_t)(ks * 32) + bKh) ^ bXor;
            uint32_t bh[8];
            ldsm4(bh + 0, bRow0 + kbB);
            ldsm4(bh + 4, bRow1 + kbB);
            uint32_t kbA = ((uint32_t)(ks * 32) + aKh) ^ aXor;
#pragma unroll
            for (int mt = 0; mt < 4; mt++) {
                uint32_t ah[4];
                ldsm4(ah, aRowBase + (uint32_t)(mt * 16) * 256u + kbA);
#pragma unroll
                for (int ng = 0; ng < 4; ng++)
                    mma16816(acc[mt][ng], ah, bh + ng * 2);
            }
        }
        __syncthreads();   // A free; KV aliases it

        // ---- phase 3: K-warps stage K; V-warps build segment list ----
        if (isK) {
#pragma unroll
            for (int mt = 0; mt < 4; mt++) {
#pragma unroll
                for (int ng = 0; ng < 4; ng++) {
                    int ee = warp_row * 64 + mt * 16 + r4;
                    unsigned jb = (unsigned)((n0 + ng * 8 + c2) * 4);
                    char* base = smc + OFF_KV;
                    *(float2*)(base + ee * 512 + (jb ^ ((unsigned)(ee & 31) << 4))) =
                        make_float2(acc[mt][ng][0], acc[mt][ng][1]);
                    int ee2 = ee + 8;
                    *(float2*)(base + ee2 * 512 + (jb ^ ((unsigned)(ee2 & 31) << 4))) =
                        make_float2(acc[mt][ng][2], acc[mt][ng][3]);
                }
            }
        } else {
            int e = tid - 256;
            if (e >= 0 && e < 128) {
                bool bnd = (e < cnt) && (e == 0 || dst_s[e] != dst_s[e - 1]);
                if (bnd) {
                    int s = atomicAdd(nseg_p, 1);
                    seg_s[s] = e;
                }
            }
        }
        __syncthreads();

        // ---- phase 4: scores, coalesced Q rows, warp per 8 edges ----
        {
#pragma unroll
            for (int e = 0; e < 8; e++) {
                int ge = ew0 + e;
                int d2 = dst_s[ge];
                float sce = ss_s[ge];
                float4 q4 = __ldg((const float4*)(g_Q + (size_t)d2 * H) + lane);
                char* kbase = smc + OFF_KV + ge * 512;
                float4 kr = *(float4*)(kbase + (((unsigned)(lane * 16)) ^ ((unsigned)(ge & 31) << 4)));
                float k0 = fmaf(kr.x, sce, bk4.x);
                float k1 = fmaf(kr.y, sce, bk4.y);
                float k2 = fmaf(kr.z, sce, bk4.z);
                float k3 = fmaf(kr.w, sce, bk4.w);
                float dp = q4.x * k0 + q4.y * k1 + q4.z * k2 + q4.w * k3;
                dp += __shfl_xor_sync(0xFFFFFFFFu, dp, 1);
                dp += __shfl_xor_sync(0xFFFFFFFFu, dp, 2);
                if ((lane & 3) == 0) w_sm[ge * 8 + head] = expf(dp * 0.25f);
            }
        }
        __syncthreads();

        int ns = nseg_p[0];

        // ---- phase 5: V-warps stage V; K-warps segmented denom ----
        if (!isK) {
#pragma unroll
            for (int mt = 0; mt < 4; mt++) {
#pragma unroll
                for (int ng = 0; ng < 4; ng++) {
                    int ee = warp_row * 64 + mt * 16 + r4;
                    unsigned jb = (unsigned)((n0 - 128 + ng * 8 + c2) * 4);
                    char* base = smc + OFF_KV;
                    *(float2*)(base + ee * 512 + (jb ^ ((unsigned)(ee & 31) << 4))) =
                        make_float2(acc[mt][ng][0], acc[mt][ng][1]);
                    int ee2 = ee + 8;
                    *(float2*)(base + ee2 * 512 + (jb ^ ((unsigned)(ee2 & 31) << 4))) =
                        make_float2(acc[mt][ng][2], acc[mt][ng][3]);
                }
            }
        } else {
            for (int idx = tid; idx < ns * NHEAD; idx += 256) {
                int s = idx >> 3, h = idx & 7;
                int st = seg_s[s];
                int d = dst_s[st];
                int gs = __ldg(&g_offs[d]), gend = __ldg(&g_offs[d + 1]);
                int lend = min(cnt, gend - e0);
                float sum = 0.f;
                for (int e = st; e < lend; e++) sum += w_sm[e * 8 + h];
                bool interior = (gs >= e0) && (gend <= e0 + cnt);
                if (interior) g_denom[(size_t)d * NHEAD + h] = sum;
                else atomicAdd(&g_denom[(size_t)d * NHEAD + h], sum);
            }
        }
        __syncthreads();

        // ---- phase 6: segmented V reduce, warp per segment ----
        {
            int hh = head;
            for (int s = wid; s < ns; s += 16) {
                int st = seg_s[s];
                int d = dst_s[st];
                int gs = __ldg(&g_offs[d]), gend = __ldg(&g_offs[d + 1]);
                int lend = min(cnt, gend - e0);
                bool interior = (gs >= e0) && (gend <= e0 + cnt);
                float4 a4 = make_float4(0.f, 0.f, 0.f, 0.f);
                for (int e = st; e < lend; e++) {
                    float sce = ss_s[e];
                    float ww = w_sm[e * 8 + hh];
                    char* vrow = smc + OFF_KV + e * 512;
                    float4 vr = *(float4*)(vrow + (((unsigned)(lane * 16)) ^ ((unsigned)(e & 31) << 4)));
                    a4.x += fmaf(vr.x, sce, bv4.x) * ww;
                    a4.y += fmaf(vr.y, sce, bv4.y) * ww;
                    a4.z += fmaf(vr.z, sce, bv4.z) * ww;
                    a4.w += fmaf(vr.w, sce, bv4.w) * ww;
                }
                float* orow = out + (size_t)d * H + lane * 4;
                if (interior) *(float4*)orow = a4;
                else REDV4(orow, a4.x, a4.y, a4.z, a4.w);
            }
        }
        __syncthreads();
    }
}

// ---------------- normalize + re-zero hist ---------------------------------
__global__ void k_norm(float* __restrict__ out, int N)
{
    int idx = blockIdx.x * blockDim.x + threadIdx.x;
    if (idx < N) g_hist[idx] = 0;
    if (idx >= N * H) return;
    int n = idx >> 7, jj = idx & (H - 1);
    float dnm = g_denom[n * NHEAD + (jj >> 4)];
    float v = out[idx];
    out[idx] = (dnm > 0.f) ? v / dnm : 0.f;
}

// ---------------- launch ---------------------------------------------------
extern "C" void kernel_launch(void* const* d_in, const int* in_sizes, int n_in,
                              void* d_out, int out_size)
{
    const float* x     = (const float*)d_in[0];
    const float* ts    = (const float*)d_in[1];
    const int*   src   = (const int*)  d_in[2];
    const int*   dst   = (const int*)  d_in[3];
    const int*   etyp  = (const int*)  d_in[4];
    const float* etime = (const float*)d_in[5];
    const float* rel   = (const float*)d_in[6];
    const float* Wq    = (const float*)d_in[7];
    const float* bq    = (const float*)d_in[8];
    const float* Wk    = (const float*)d_in[9];
    const float* bk    = (const float*)d_in[10];
    const float* Wv    = (const float*)d_in[11];
    const float* bv    = (const float*)d_in[12];
    const float* W1    = (const float*)d_in[13];
    const float* b1    = (const float*)d_in[14];
    const float* W2    = (const float*)d_in[15];
    const float* b2    = (const float*)d_in[16];
    const float* tcp   = (const float*)d_in[17];

    int N    = in_sizes[0] / H;
    int E    = in_sizes[2];
    int NREL = in_sizes[6] / H;
    float* out = (float*)d_out;
    int ntiles = (E + TILE_E - 1) / TILE_E;

    int NB_SC = (E + 255) / 256;
    int NB_PW = 128;
    int NB_RL = (NREL + 1) / 2;
    int NB_ND = ((N + TEN - 1) / TEN + 1) / 2;
    int NB = NB_SC + NB_PW + NB_RL + NB_ND;

    static int smem_set = 0;
    if (!smem_set) {
        cudaFuncSetAttribute(k_edge_mma, cudaFuncAttributeMaxDynamicSharedMemorySize, SMEM_EDGE);
        smem_set = 1;
    }

    k_pre1<<<2048, 256>>>(dst, out, N, E, out_size);
    k_scan<<<1, 1024>>>(N, E);
    k_pre3<<<NB, 256>>>(dst, src, x, Wq, bq, W1, rel, Wk, Wv,
                        N, E, NREL, NB_SC, NB_PW, NB_RL);
    k_edge_mma<<<148, NT, SMEM_EDGE>>>(x, ts, src, dst, etyp, etime, rel,
                                       bk, bv, b1, W2, b2, tcp, out, E, ntiles);
    k_norm<<<(N * H + 255) / 256, 256>>>(out, N);
}

// round 14
// speedup vs baseline: 2.2538x; 1.1260x over previous
#include <cuda_runtime.h>
#include <cuda_fp16.h>
#include <cstdint>

#define H       128
#define NHEAD   8
#define N_MAX   50000
#define E_MAX   800000
#define NRELMX  64
#define TILE_E  128
#define NT      512

// ---------------- global scratch -------------------------------------------
__device__ float g_Q  [N_MAX * H];
__device__ float g_S1 [N_MAX * H];
__device__ float g_R2x[NRELMX * H];
__device__ float g_denom[N_MAX * NHEAD];
__device__ __half g_B [256 * H];       // [Wk|Wv] image, 256B rows, XOR-16B swizzle
__device__ __half g_BN[256 * H];       // [Wq|W1a] image, same format
__device__ int   g_hist[N_MAX];        // zero at module load; re-zeroed by k_norm
__device__ int   g_offs[N_MAX + 1];
__device__ int   g_offsw[N_MAX];
__device__ int   g_perm[E_MAX];

// ---------------- smem layout (edge kernel) --------------------------------
#define OFF_B     0        // 65536
#define OFF_A     65536    // 32768 (fp16 A tile)
#define OFF_KV    65536    // 65536 (aliases A region after GEMM)
#define OFF_BK    131072
#define OFF_BV    131584
#define OFF_B1    132096
#define OFF_W2    132608
#define OFF_DST   133120
#define OFF_SS    133632
#define OFF_WS    134144   // w_sm[128][8] = 4096
#define OFF_SEG   138240   // 128 ints
#define OFF_NSEG  138752
#define SMEM_EDGE 139264

// node kernel smem
#define NOFF_BQ   131072
#define SMEM_NODE 131584

// ---------------- helpers --------------------------------------------------
__device__ __forceinline__ uint32_t s2u(const void* p) {
    uint32_t a;
    asm("{ .reg .u64 t; cvta.to.shared.u64 t, %1; cvt.u32.u64 %0, t; }" : "=r"(a) : "l"(p));
    return a;
}
__device__ __forceinline__ void ldsm4(uint32_t* r, uint32_t addr) {
    asm volatile("ldmatrix.sync.aligned.m8n8.x4.shared.b16 {%0,%1,%2,%3}, [%4];"
                 : "=r"(r[0]), "=r"(r[1]), "=r"(r[2]), "=r"(r[3]) : "r"(addr));
}
__device__ __forceinline__ void mma16816(float* c, const uint32_t* a, const uint32_t* b) {
    asm volatile(
        "mma.sync.aligned.m16n8k16.row.col.f32.f16.f16.f32 "
        "{%0,%1,%2,%3}, {%4,%5,%6,%7}, {%8,%9}, {%0,%1,%2,%3};"
        : "+f"(c[0]), "+f"(c[1]), "+f"(c[2]), "+f"(c[3])
        : "r"(a[0]), "r"(a[1]), "r"(a[2]), "r"(a[3]), "r"(b[0]), "r"(b[1]));
}
#define REDV4(p, a, b, c, d) asm volatile("red.global.add.v4.f32 [%0], {%1,%2,%3,%4};" :: "l"(p), "f"(a), "f"(b), "f"(c), "f"(d) : "memory")

// ---------------- pre1: zero out+denom, histogram dst ----------------------
__global__ void k_pre1(const int* __restrict__ dst, float* __restrict__ out,
                       int N, int E, int outElems) {
    int i = blockIdx.x * blockDim.x + threadIdx.x;
    int stride = gridDim.x * blockDim.x;
    for (int idx = i; idx < outElems; idx += stride) out[idx] = 0.f;
    for (int idx = i; idx < N * NHEAD; idx += stride) g_denom[idx] = 0.f;
    for (int idx = i; idx < E; idx += stride) atomicAdd(&g_hist[dst[idx]], 1);
}

// ---------------- scan: exclusive prefix over hist (1 CTA) -----------------
__global__ void __launch_bounds__(1024) k_scan(int N, int E) {
    __shared__ int sm[1024];
    int t = threadIdx.x;
    int chunk = (N + 1023) >> 10;
    int base = t * chunk;
    int s = 0;
    for (int i = 0; i < chunk; i++) {
        int ix = base + i;
        if (ix < N) s += g_hist[ix];
    }
    sm[t] = s;
    __syncthreads();
    for (int off = 1; off < 1024; off <<= 1) {
        int v = (t >= off) ? sm[t - off] : 0;
        __syncthreads();
        sm[t] += v;
        __syncthreads();
    }
    int run = sm[t] - s;
    for (int i = 0; i < chunk; i++) {
        int ix = base + i;
        if (ix < N) {
            g_offs[ix] = run;
            g_offsw[ix] = run;
            run += g_hist[ix];
        }
    }
    if (t == 0) g_offs[N] = E;
}

// ---------------- pre3: scatter-perm + weight images + R2x -----------------
__global__ void k_pre3(
    const int* __restrict__ dst,
    const float* __restrict__ Wq, const float* __restrict__ W1,
    const float* __restrict__ rel,
    const float* __restrict__ Wk, const float* __restrict__ Wv,
    int N, int E, int NREL, int NB_SC, int NB_PW)
{
    int b = blockIdx.x, tid = threadIdx.x;
    if (b < NB_SC) {
        int e = b * 256 + tid;
        if (e < E) {
            int d = dst[e];
            int pos = atomicAdd(&g_offsw[d], 1);
            g_perm[pos] = e;
        }
        return;
    }
    b -= NB_SC;
    if (b < NB_PW) {
        // 512 image rows: 0-255 -> g_B ([Wk|Wv]), 256-511 -> g_BN ([Wq|W1a])
        int n = b * 2 + (tid >> 7);
        int k = tid & 127;
        unsigned kb = (unsigned)k * 2u;
        if (n < 256) {
            float w = (n < H) ? Wk[k * H + n] : Wv[k * H + (n - H)];
            unsigned phys = (unsigned)n * 256u + (kb ^ ((unsigned)(n & 7) << 4));
            *(__half*)((char*)g_B + phys) = __float2half_rn(w);
        } else {
            int m = n - 256;
            float w = (m < H) ? Wq[k * H + m] : W1[k * H + (m - H)];
            unsigned phys = (unsigned)m * 256u + (kb ^ ((unsigned)(m & 7) << 4));
            *(__half*)((char*)g_BN + phys) = __float2half_rn(w);
        }
        return;
    }
    b -= NB_PW;
    {
        int r = b * 2 + (tid >> 7);
        int j = tid & 127;
        if (r < NREL) {
            float acc = W1[256 * H + j];
            for (int i = 0; i < H; i++)
                acc += rel[r * H + i] * W1[(H + i) * H + j];
            g_R2x[r * H + j] = acc;
        }
    }
}

// ---------------- node GEMM: Q = x@Wq+bq, S1 = x@W1a (fp16 mma) ------------
__global__ void __launch_bounds__(NT, 1) k_nodemma(
    const float* __restrict__ x, const float* __restrict__ bq, int N)
{
    extern __shared__ __align__(1024) char smc[];
    uint32_t smb = s2u(smc);
    int tid = threadIdx.x, wid = tid >> 5, lane = tid & 31;

    // stage B image
    {
        float4* d0 = (float4*)(smc + OFF_B);
        const float4* s0 = (const float4*)g_BN;
        for (int i = tid; i < 4096; i += NT) d0[i] = s0[i];
    }
    if (tid < H) ((float*)(smc + NOFF_BQ))[tid] = bq[tid];
    __syncthreads();

    int n0t = blockIdx.x * 128;
    int cnt = min(128, N - n0t);

    int warp_row = wid & 1;
    int warp_col = wid >> 1;
    int n0 = warp_col * 32;
    bool isQ = (n0 < 128);

    int ra = lane & 7, ha = (lane >> 3) & 1, kh = lane >> 4;
    uint32_t aXor = (uint32_t)ra << 4;
    uint32_t aKh = (uint32_t)(kh * 16);
    uint32_t aRowBase = smb + OFF_A + (uint32_t)(warp_row * 64 + ha * 8 + ra) * 256u;

    int qb = lane >> 3, rb = lane & 7;
    uint32_t bXor = (uint32_t)rb << 4;
    uint32_t bKh = (uint32_t)((qb & 1) * 16);
    uint32_t bRow0 = smb + OFF_B + (uint32_t)(n0 + (qb >> 1) * 8 + rb) * 256u;
    uint32_t bRow1 = bRow0 + 16u * 256u;

    int r4 = lane >> 2, c2 = (lane & 3) * 2;
    int ew0 = wid * 8;

    // ---- phase 1: load x rows -> fp16 A ----
#pragma unroll
    for (int e = 0; e < 8; e++) {
        int ge = ew0 + e;
        int row = (ge < cnt) ? (n0t + ge) : n0t;
        float4 xv = __ldg((const float4*)(x + (size_t)row * H) + lane);
        __half2 h01 = __floats2half2_rn(xv.x, xv.y);
        __half2 h23 = __floats2half2_rn(xv.z, xv.w);
        char* Ah = smc + OFF_A + ge * 256;
        unsigned kb = (unsigned)(lane * 8);
        unsigned xr = (unsigned)(ge & 7) << 4;
        uint2 uh; uh.x = *(unsigned*)&h01; uh.y = *(unsigned*)&h23;
        *(uint2*)(Ah + (kb ^ xr)) = uh;
    }
    __syncthreads();

    // ---- phase 2: GEMM 128x256x128 ----
    float acc[4][4][4];
#pragma unroll
    for (int mt = 0; mt < 4; mt++)
#pragma unroll
        for (int ng = 0; ng < 4; ng++)
#pragma unroll
            for (int i = 0; i < 4; i++) acc[mt][ng][i] = 0.f;

    for (int ks = 0; ks < 8; ks++) {
        uint32_t kbB = ((uint32_t)(ks * 32) + bKh) ^ bXor;
        uint32_t bh[8];
        ldsm4(bh + 0, bRow0 + kbB);
        ldsm4(bh + 4, bRow1 + kbB);
        uint32_t kbA = ((uint32_t)(ks * 32) + aKh) ^ aXor;
#pragma unroll
        for (int mt = 0; mt < 4; mt++) {
            uint32_t ah[4];
            ldsm4(ah, aRowBase + (uint32_t)(mt * 16) * 256u + kbA);
#pragma unroll
            for (int ng = 0; ng < 4; ng++)
                mma16816(acc[mt][ng], ah, bh + ng * 2);
        }
    }
    __syncthreads();   // A free; KV stage aliases

    float4 bq4 = *(const float4*)((float*)(smc + NOFF_BQ) + lane * 4);

    // ---- pass Q: stage cols 0-127, write g_Q ----
    if (isQ) {
#pragma unroll
        for (int mt = 0; mt < 4; mt++) {
#pragma unroll
            for (int ng = 0; ng < 4; ng++) {
                int ee = warp_row * 64 + mt * 16 + r4;
                unsigned jb = (unsigned)((n0 + ng * 8 + c2) * 4);
                char* base = smc + OFF_KV;
                *(float2*)(base + ee * 512 + (jb ^ ((unsigned)(ee & 31) << 4))) =
                    make_float2(acc[mt][ng][0], acc[mt][ng][1]);
                int ee2 = ee + 8;
                *(float2*)(base + ee2 * 512 + (jb ^ ((unsigned)(ee2 & 31) << 4))) =
                    make_float2(acc[mt][ng][2], acc[mt][ng][3]);
            }
        }
    }
    __syncthreads();
#pragma unroll
    for (int e = 0; e < 8; e++) {
        int ge = ew0 + e;
        if (ge < cnt) {
            char* krow = smc + OFF_KV + ge * 512;
            float4 v = *(float4*)(krow + (((unsigned)(lane * 16)) ^ ((unsigned)(ge & 31) << 4)));
            v.x += bq4.x; v.y += bq4.y; v.z += bq4.z; v.w += bq4.w;
            *(float4*)(g_Q + (size_t)(n0t + ge) * H + lane * 4) = v;
        }
    }
    __syncthreads();

    // ---- pass S1: stage cols 128-255, write g_S1 ----
    if (!isQ) {
#pragma unroll
        for (int mt = 0; mt < 4; mt++) {
#pragma unroll
            for (int ng = 0; ng < 4; ng++) {
                int ee = warp_row * 64 + mt * 16 + r4;
                unsigned jb = (unsigned)((n0 - 128 + ng * 8 + c2) * 4);
                char* base = smc + OFF_KV;
                *(float2*)(base + ee * 512 + (jb ^ ((unsigned)(ee & 31) << 4))) =
                    make_float2(acc[mt][ng][0], acc[mt][ng][1]);
                int ee2 = ee + 8;
                *(float2*)(base + ee2 * 512 + (jb ^ ((unsigned)(ee2 & 31) << 4))) =
                    make_float2(acc[mt][ng][2], acc[mt][ng][3]);
            }
        }
    }
    __syncthreads();
#pragma unroll
    for (int e = 0; e < 8; e++) {
        int ge = ew0 + e;
        if (ge < cnt) {
            char* vrow = smc + OFF_KV + ge * 512;
            float4 v = *(float4*)(vrow + (((unsigned)(lane * 16)) ^ ((unsigned)(ge & 31) << 4)));
            *(float4*)(g_S1 + (size_t)(n0t + ge) * H + lane * 4) = v;
        }
    }
}

// ---------------- persistent fused edge kernel -----------------------------
__global__ void __launch_bounds__(NT, 1) k_edge_mma(
    const float* __restrict__ x, const float* __restrict__ ts,
    const int* __restrict__ src, const int* __restrict__ dst, const int* __restrict__ et,
    const float* __restrict__ etime, const float* __restrict__ rel,
    const float* __restrict__ bk, const float* __restrict__ bv,
    const float* __restrict__ b1, const float* __restrict__ W2,
    const float* __restrict__ b2, const float* __restrict__ tcp,
    float* __restrict__ out, int E, int ntiles)
{
    extern __shared__ __align__(1024) char smc[];
    uint32_t smb = s2u(smc);
    int tid = threadIdx.x, wid = tid >> 5, lane = tid & 31;

    float* bk_s  = (float*)(smc + OFF_BK);
    float* bv_s  = (float*)(smc + OFF_BV);
    float* b1_s  = (float*)(smc + OFF_B1);
    float* w2_s  = (float*)(smc + OFF_W2);
    int*   dst_s = (int*)  (smc + OFF_DST);
    float* ss_s  = (float*)(smc + OFF_SS);
    float* w_sm  = (float*)(smc + OFF_WS);
    int*   seg_s = (int*)  (smc + OFF_SEG);
    int*   nseg_p= (int*)  (smc + OFF_NSEG);

    {
        float4* d0 = (float4*)(smc + OFF_B);
        const float4* s0 = (const float4*)g_B;
        for (int i = tid; i < 4096; i += NT) d0[i] = s0[i];
    }
    if (tid < H) { bk_s[tid] = bk[tid]; bv_s[tid] = bv[tid]; b1_s[tid] = b1[tid]; w2_s[tid] = W2[tid]; }
    __syncthreads();

    float inv_tc = 1.f / (fabsf(tcp[0]) + 1e-9f);
    float b2v = b2[0];

    int warp_row = wid & 1;
    int warp_col = wid >> 1;
    int n0 = warp_col * 32;
    bool isK = (n0 < 128);

    int ra = lane & 7, ha = (lane >> 3) & 1, kh = lane >> 4;
    uint32_t aXor = (uint32_t)ra << 4;
    uint32_t aKh = (uint32_t)(kh * 16);
    uint32_t aRowBase = smb + OFF_A + (uint32_t)(warp_row * 64 + ha * 8 + ra) * 256u;

    int qb = lane >> 3, rb = lane & 7;
    uint32_t bXor = (uint32_t)rb << 4;
    uint32_t bKh = (uint32_t)((qb & 1) * 16);
    uint32_t bRow0 = smb + OFF_B + (uint32_t)(n0 + (qb >> 1) * 8 + rb) * 256u;
    uint32_t bRow1 = bRow0 + 16u * 256u;

    int r4 = lane >> 2, c2 = (lane & 3) * 2;
    int ew0 = wid * 8;

    float4 b14 = *(const float4*)(b1_s + lane * 4);
    float4 w24 = *(const float4*)(w2_s + lane * 4);
    float4 bk4 = *(const float4*)(bk_s + lane * 4);
    float4 bv4 = *(const float4*)(bv_s + lane * 4);
    int head = lane >> 2;

    for (int t = blockIdx.x; t < ntiles; t += gridDim.x) {
        int e0 = t * TILE_E;
        int cnt = min(TILE_E, E - e0);

        // ---- phase 1: meta + coalesced row gather + batched gating reduce ----
        {
            int sn = 0, rr = 0, dd = 0;
            float tme = 0.f;
            if (lane < 8) {
                int ge = ew0 + lane;
                if (ge < cnt) {
                    int ee = __ldg(&g_perm[e0 + ge]);
                    dd = dst[ee];
                    sn = src[ee]; rr = et[ee];
                    float dt = (ts[dd] - etime[ee]) * inv_tc;
                    tme = 1.f / (1.f + expf(-dt));
                }
                dst_s[ge] = dd;
            }
            float pe[8];
#pragma unroll
            for (int e = 0; e < 8; e++) {
                int ge = ew0 + e;
                int sne = __shfl_sync(0xFFFFFFFFu, sn, e);
                int rre = __shfl_sync(0xFFFFFFFFu, rr, e);
                float tmee = __shfl_sync(0xFFFFFFFFu, tme, e);
                float4 xv = __ldg((const float4*)(x     + (size_t)sne * H) + lane);
                float4 rv = __ldg((const float4*)(rel   + (size_t)rre * H) + lane);
                float4 s1 = __ldg((const float4*)(g_S1  + (size_t)sne * H) + lane);
                float4 r2 = __ldg((const float4*)(g_R2x + (size_t)rre * H) + lane);
                float g0 = xv.x * rv.x, g1 = xv.y * rv.y, g2 = xv.z * rv.z, g3 = xv.w * rv.w;
                float p;
                p  = fmaxf(fmaf(tmee, r2.x, s1.x + b14.x), 0.f) * w24.x;
                p += fmaxf(fmaf(tmee, r2.y, s1.y + b14.y), 0.f) * w24.y;
                p += fmaxf(fmaf(tmee, r2.z, s1.z + b14.z), 0.f) * w24.z;
                p += fmaxf(fmaf(tmee, r2.w, s1.w + b14.w), 0.f) * w24.w;
                pe[e] = p;
                __half2 h01 = __floats2half2_rn(g0, g1);
                __half2 h23 = __floats2half2_rn(g2, g3);
                char* Ah = smc + OFF_A + ge * 256;
                unsigned kb = (unsigned)(lane * 8);
                unsigned xr = (unsigned)(ge & 7) << 4;
                uint2 uh; uh.x = *(unsigned*)&h01; uh.y = *(unsigned*)&h23;
                *(uint2*)(Ah + (kb ^ xr)) = uh;
            }
            // batched reduction: 8 independent warp sums
#pragma unroll
            for (int off = 16; off >= 1; off >>= 1) {
#pragma unroll
                for (int e = 0; e < 8; e++)
                    pe[e] += __shfl_xor_sync(0xFFFFFFFFu, pe[e], off);
            }
            if (lane < 8) {
                float hsum = pe[0];
#pragma unroll
                for (int i = 1; i < 8; i++) hsum = (lane == i) ? pe[i] : hsum;
                float dw = 1.f / (1.f + expf(-(hsum + b2v)));
                ss_s[ew0 + lane] = tme * dw;
            }
        }
        if (tid == 0) nseg_p[0] = 0;
        __syncthreads();

        // ---- phase 2: GEMM 128x256x128 fp16 ----
        float acc[4][4][4];
#pragma unroll
        for (int mt = 0; mt < 4; mt++)
#pragma unroll
            for (int ng = 0; ng < 4; ng++)
#pragma unroll
                for (int i = 0; i < 4; i++) acc[mt][ng][i] = 0.f;

        for (int ks = 0; ks < 8; ks++) {
            uint32_t kbB = ((uint32_t)(ks * 32) + bKh) ^ bXor;
            uint32_t bh[8];
            ldsm4(bh + 0, bRow0 + kbB);
            ldsm4(bh + 4, bRow1 + kbB);
            uint32_t kbA = ((uint32_t)(ks * 32) + aKh) ^ aXor;
#pragma unroll
            for (int mt = 0; mt < 4; mt++) {
                uint32_t ah[4];
                ldsm4(ah, aRowBase + (uint32_t)(mt * 16) * 256u + kbA);
#pragma unroll
                for (int ng = 0; ng < 4; ng++)
                    mma16816(acc[mt][ng], ah, bh + ng * 2);
            }
        }
        __syncthreads();

        // ---- phase 3: K-warps stage K; V-warps build segment list ----
        if (isK) {
#pragma unroll
            for (int mt = 0; mt < 4; mt++) {
#pragma unroll
                for (int ng = 0; ng < 4; ng++) {
                    int ee = warp_row * 64 + mt * 16 + r4;
                    unsigned jb = (unsigned)((n0 + ng * 8 + c2) * 4);
                    char* base = smc + OFF_KV;
                    *(float2*)(base + ee * 512 + (jb ^ ((unsigned)(ee & 31) << 4))) =
                        make_float2(acc[mt][ng][0], acc[mt][ng][1]);
                    int ee2 = ee + 8;
                    *(float2*)(base + ee2 * 512 + (jb ^ ((unsigned)(ee2 & 31) << 4))) =
                        make_float2(acc[mt][ng][2], acc[mt][ng][3]);
                }
            }
        } else {
            int e = tid - 256;
            if (e >= 0 && e < 128) {
                bool bnd = (e < cnt) && (e == 0 || dst_s[e] != dst_s[e - 1]);
                if (bnd) {
                    int s = atomicAdd(nseg_p, 1);
                    seg_s[s] = e;
                }
            }
        }
        __syncthreads();

        // ---- phase 4: scores ----
        {
#pragma unroll
            for (int e = 0; e < 8; e++) {
                int ge = ew0 + e;
                int d2 = dst_s[ge];
                float sce = ss_s[ge];
                float4 q4 = __ldg((const float4*)(g_Q + (size_t)d2 * H) + lane);
                char* kbase = smc + OFF_KV + ge * 512;
                float4 kr = *(float4*)(kbase + (((unsigned)(lane * 16)) ^ ((unsigned)(ge & 31) << 4)));
                float k0 = fmaf(kr.x, sce, bk4.x);
                float k1 = fmaf(kr.y, sce, bk4.y);
                float k2 = fmaf(kr.z, sce, bk4.z);
                float k3 = fmaf(kr.w, sce, bk4.w);
                float dp = q4.x * k0 + q4.y * k1 + q4.z * k2 + q4.w * k3;
                dp += __shfl_xor_sync(0xFFFFFFFFu, dp, 1);
                dp += __shfl_xor_sync(0xFFFFFFFFu, dp, 2);
                if ((lane & 3) == 0) w_sm[ge * 8 + head] = expf(dp * 0.25f);
            }
        }
        __syncthreads();

        int ns = nseg_p[0];

        // ---- phase 5: V-warps stage V; K-warps segmented denom ----
        if (!isK) {
#pragma unroll
            for (int mt = 0; mt < 4; mt++) {
#pragma unroll
                for (int ng = 0; ng < 4; ng++) {
                    int ee = warp_row * 64 + mt * 16 + r4;
                    unsigned jb = (unsigned)((n0 - 128 + ng * 8 + c2) * 4);
                    char* base = smc + OFF_KV;
                    *(float2*)(base + ee * 512 + (jb ^ ((unsigned)(ee & 31) << 4))) =
                        make_float2(acc[mt][ng][0], acc[mt][ng][1]);
                    int ee2 = ee + 8;
                    *(float2*)(base + ee2 * 512 + (jb ^ ((unsigned)(ee2 & 31) << 4))) =
                        make_float2(acc[mt][ng][2], acc[mt][ng][3]);
                }
            }
        } else {
            for (int idx = tid; idx < ns * NHEAD; idx += 256) {
                int s = idx >> 3, h = idx & 7;
                int st = seg_s[s];
                int d = dst_s[st];
                int gs = __ldg(&g_offs[d]), gend = __ldg(&g_offs[d + 1]);
                int lend = min(cnt, gend - e0);
                float sum = 0.f;
                for (int e = st; e < lend; e++) sum += w_sm[e * 8 + h];
                bool interior = (gs >= e0) && (gend <= e0 + cnt);
                if (interior) g_denom[(size_t)d * NHEAD + h] = sum;
                else atomicAdd(&g_denom[(size_t)d * NHEAD + h], sum);
            }
        }
        __syncthreads();

        // ---- phase 6: segmented V reduce ----
        {
            int hh = head;
            for (int s = wid; s < ns; s += 16) {
                int st = seg_s[s];
                int d = dst_s[st];
                int gs = __ldg(&g_offs[d]), gend = __ldg(&g_offs[d + 1]);
                int lend = min(cnt, gend - e0);
                bool interior = (gs >= e0) && (gend <= e0 + cnt);
                float4 a4 = make_float4(0.f, 0.f, 0.f, 0.f);
                for (int e = st; e < lend; e++) {
                    float sce = ss_s[e];
                    float ww = w_sm[e * 8 + hh];
                    char* vrow = smc + OFF_KV + e * 512;
                    float4 vr = *(float4*)(vrow + (((unsigned)(lane * 16)) ^ ((unsigned)(e & 31) << 4)));
                    a4.x += fmaf(vr.x, sce, bv4.x) * ww;
                    a4.y += fmaf(vr.y, sce, bv4.y) * ww;
                    a4.z += fmaf(vr.z, sce, bv4.z) * ww;
                    a4.w += fmaf(vr.w, sce, bv4.w) * ww;
                }
                float* orow = out + (size_t)d * H + lane * 4;
                if (interior) *(float4*)orow = a4;
                else REDV4(orow, a4.x, a4.y, a4.z, a4.w);
            }
        }
        __syncthreads();
    }
}

// ---------------- normalize + re-zero hist ---------------------------------
__global__ void k_norm(float* __restrict__ out, int N)
{
    int idx = blockIdx.x * blockDim.x + threadIdx.x;
    if (idx < N) g_hist[idx] = 0;
    if (idx >= N * H) return;
    int n = idx >> 7, jj = idx & (H - 1);
    float dnm = g_denom[n * NHEAD + (jj >> 4)];
    float v = out[idx];
    out[idx] = (dnm > 0.f) ? v / dnm : 0.f;
}

// ---------------- launch ---------------------------------------------------
extern "C" void kernel_launch(void* const* d_in, const int* in_sizes, int n_in,
                              void* d_out, int out_size)
{
    const float* x     = (const float*)d_in[0];
    const float* ts    = (const float*)d_in[1];
    const int*   src   = (const int*)  d_in[2];
    const int*   dst   = (const int*)  d_in[3];
    const int*   etyp  = (const int*)  d_in[4];
    const float* etime = (const float*)d_in[5];
    const float* rel   = (const float*)d_in[6];
    const float* Wq    = (const float*)d_in[7];
    const float* bq    = (const float*)d_in[8];
    const float* Wk    = (const float*)d_in[9];
    const float* bk    = (const float*)d_in[10];
    const float* Wv    = (const float*)d_in[11];
    const float* bv    = (const float*)d_in[12];
    const float* W1    = (const float*)d_in[13];
    const float* b1    = (const float*)d_in[14];
    const float* W2    = (const float*)d_in[15];
    const float* b2    = (const float*)d_in[16];
    const float* tcp   = (const float*)d_in[17];

    int N    = in_sizes[0] / H;
    int E    = in_sizes[2];
    int NREL = in_sizes[6] / H;
    float* out = (float*)d_out;
    int ntiles = (E + TILE_E - 1) / TILE_E;

    int NB_SC = (E + 255) / 256;
    int NB_PW = 256;
    int NB_RL = (NREL + 1) / 2;
    int NB = NB_SC + NB_PW + NB_RL;

    static int smem_set = 0;
    if (!smem_set) {
        cudaFuncSetAttribute(k_edge_mma, cudaFuncAttributeMaxDynamicSharedMemorySize, SMEM_EDGE);
        cudaFuncSetAttribute(k_nodemma, cudaFuncAttributeMaxDynamicSharedMemorySize, SMEM_NODE);
        smem_set = 1;
    }

    k_pre1<<<2048, 256>>>(dst, out, N, E, out_size);
    k_scan<<<1, 1024>>>(N, E);
    k_pre3<<<NB, 256>>>(dst, Wq, W1, rel, Wk, Wv, N, E, NREL, NB_SC, NB_PW);
    k_nodemma<<<(N + 127) / 128, NT, SMEM_NODE>>>(x, bq, N);
    k_edge_mma<<<148, NT, SMEM_EDGE>>>(x, ts, src, dst, etyp, etime, rel,
                                       bk, bv, b1, W2, b2, tcp, out, E, ntiles);
    k_norm<<<(N * H + 255) / 256, 256>>>(out, N);
}